// round 1
// baseline (speedup 1.0000x reference)
#include <cuda_runtime.h>
#include <math.h>
#include <float.h>
#include <stdint.h>

// ---------------- model constants ----------------
#define VCAB 50257
#define DM   768
#define NL   6
#define NH   12
#define HDIM 64
#define BBAT 4
#define TSEQ 512
#define NTOK (BBAT * TSEQ)     // 2048
#define DFF  (4 * DM)          // 3072

// ---------------- scratch (device globals: allocation-free) ----------------
__device__ float g_x   [NTOK * DM];
__device__ float g_h   [NTOK * DM];
__device__ float g_h2  [NTOK * DM];
__device__ float g_q   [NTOK * DM];
__device__ float g_k   [NTOK * DM];
__device__ float g_v   [NTOK * DM];
__device__ float g_attn[NTOK * DM];
__device__ float g_ff  [NTOK * DFF];
__device__ float g_scores[(size_t)BBAT * NH * TSEQ * TSEQ];
__device__ float g_wq[NL * DM * DM];
__device__ float g_wk[NL * DM * DM];
__device__ float g_wv[NL * DM * DM];
__device__ float g_nll[NTOK];
__device__ float g_logits_scratch[(size_t)NTOK * VCAB];  // fallback if d_out is loss-only

// ---------------- embedding ----------------
__global__ void embed_kernel(const int* __restrict__ ids,
                             const float* __restrict__ tok,
                             const float* __restrict__ pos) {
    int i = blockIdx.x * blockDim.x + threadIdx.x;
    if (i >= NTOK * DM) return;
    int row = i / DM, d = i - row * DM;
    int t = row % TSEQ;
    g_x[i] = tok[(size_t)ids[row] * DM + d] + pos[t * DM + d];
}

// repack wq/wk/wv from [L,H,D,HD] -> [L, D, H*HD] so QKV are plain NN GEMMs
__global__ void repack_kernel(const float* __restrict__ wq,
                              const float* __restrict__ wk,
                              const float* __restrict__ wv) {
    int i = blockIdx.x * blockDim.x + threadIdx.x;
    const int total = NL * NH * DM * HDIM;
    if (i >= total) return;
    int e = i % HDIM;
    int d = (i / HDIM) % DM;
    int h = (i / (HDIM * DM)) % NH;
    int l = i / (HDIM * DM * NH);
    int o = (l * DM + d) * DM + h * HDIM + e;
    g_wq[o] = wq[i];
    g_wk[o] = wk[i];
    g_wv[o] = wv[i];
}

// ---------------- layernorm (1 block / row) ----------------
__global__ void ln_kernel(const float* __restrict__ in, float* __restrict__ out,
                          const float* __restrict__ g, const float* __restrict__ b) {
    int row = blockIdx.x;
    const float* x = in + (size_t)row * DM;
    float s = 0.f, s2 = 0.f;
    for (int i = threadIdx.x; i < DM; i += blockDim.x) {
        float v = x[i];
        s += v; s2 += v * v;
    }
    __shared__ float rs[32], rs2[32];
    for (int o = 16; o; o >>= 1) {
        s  += __shfl_down_sync(0xffffffffu, s, o);
        s2 += __shfl_down_sync(0xffffffffu, s2, o);
    }
    int wid = threadIdx.x >> 5, lid = threadIdx.x & 31;
    if (lid == 0) { rs[wid] = s; rs2[wid] = s2; }
    __syncthreads();
    if (wid == 0) {
        int nw = blockDim.x >> 5;
        s  = (lid < nw) ? rs[lid]  : 0.f;
        s2 = (lid < nw) ? rs2[lid] : 0.f;
        for (int o = 16; o; o >>= 1) {
            s  += __shfl_down_sync(0xffffffffu, s, o);
            s2 += __shfl_down_sync(0xffffffffu, s2, o);
        }
        if (lid == 0) { rs[0] = s; rs2[0] = s2; }
    }
    __syncthreads();
    float mean = rs[0] * (1.f / DM);
    float var  = rs2[0] * (1.f / DM) - mean * mean;
    float inv  = rsqrtf(var + 1e-5f);
    float* o = out + (size_t)row * DM;
    for (int i = threadIdx.x; i < DM; i += blockDim.x)
        o[i] = (x[i] - mean) * inv * g[i] + b[i];
}

// ---------------- generic fp32 SGEMM (NN) ----------------
// C[M,N] = A[M,K] @ B[K,N] (+bias[N]) (+res[M,N]) (relu?)
// BM=128, BN=64, BK=16, 256 threads, 8x4 per-thread tile.
// M % 128 == 0 and K % 16 == 0 guaranteed by the caller; N is guarded.
#define BM 128
#define BN 64
#define BK 16

__global__ void __launch_bounds__(256)
sgemm_nn(const float* __restrict__ A, const float* __restrict__ B,
         float* __restrict__ C, int M, int N, int K,
         const float* __restrict__ bias, const float* __restrict__ res, int relu) {
    __shared__ float As[BK][BM];
    __shared__ float Bs[BK][BN];
    int tid = threadIdx.x;
    int tx = tid & 15, ty = tid >> 4;
    int m0 = blockIdx.y * BM, n0 = blockIdx.x * BN;
    float acc[8][4] = {};

    for (int kt = 0; kt < K; kt += BK) {
        #pragma unroll
        for (int i = 0; i < 2; i++) {
            int v = tid + i * 256;
            int r = v >> 2, c4 = (v & 3) * 4;
            float4 a = *(const float4*)(A + (size_t)(m0 + r) * K + kt + c4);
            As[c4 + 0][r] = a.x; As[c4 + 1][r] = a.y;
            As[c4 + 2][r] = a.z; As[c4 + 3][r] = a.w;
        }
        #pragma unroll
        for (int j = 0; j < 4; j++) {
            int k = (tid >> 6) + j * 4;
            int n = tid & 63;
            int gn = n0 + n;
            Bs[k][n] = (gn < N) ? B[(size_t)(kt + k) * N + gn] : 0.f;
        }
        __syncthreads();
        #pragma unroll
        for (int k = 0; k < BK; k++) {
            float4 a0 = *(const float4*)&As[k][ty * 8];
            float4 a1 = *(const float4*)&As[k][ty * 8 + 4];
            float4 b0 = *(const float4*)&Bs[k][tx * 4];
            float am[8] = {a0.x, a0.y, a0.z, a0.w, a1.x, a1.y, a1.z, a1.w};
            float bn[4] = {b0.x, b0.y, b0.z, b0.w};
            #pragma unroll
            for (int i = 0; i < 8; i++)
                #pragma unroll
                for (int j = 0; j < 4; j++)
                    acc[i][j] += am[i] * bn[j];
        }
        __syncthreads();
    }

    #pragma unroll
    for (int i = 0; i < 8; i++) {
        int m = m0 + ty * 8 + i;
        #pragma unroll
        for (int j = 0; j < 4; j++) {
            int n = n0 + tx * 4 + j;
            if (n < N) {
                float v = acc[i][j];
                if (bias) v += bias[n];
                if (res)  v += res[(size_t)m * N + n];
                if (relu) v = fmaxf(v, 0.f);
                C[(size_t)m * N + n] = v;
            }
        }
    }
}

// ---------------- attention scores: S[z][t,s] = K[t,:] . Q[s,:]  (NT, K=64) ----------------
// causal mask fused: s > t -> -inf
__global__ void __launch_bounds__(256)
attn_scores(const float* __restrict__ Kb, const float* __restrict__ Qb) {
    int z = blockIdx.z;
    int b = z / NH, h = z % NH;
    const float* A  = Kb + (size_t)b * TSEQ * DM + h * HDIM;   // A[t*DM + e]
    const float* Bq = Qb + (size_t)b * TSEQ * DM + h * HDIM;   // B[s*DM + e]
    float* C = g_scores + (size_t)z * TSEQ * TSEQ;

    __shared__ float As[BK][BM];
    __shared__ float Bs[BK][BN];
    int tid = threadIdx.x;
    int tx = tid & 15, ty = tid >> 4;
    int m0 = blockIdx.y * BM, n0 = blockIdx.x * BN;
    float acc[8][4] = {};

    for (int kt = 0; kt < HDIM; kt += BK) {
        #pragma unroll
        for (int i = 0; i < 2; i++) {
            int v = tid + i * 256;
            int r = v >> 2, c4 = (v & 3) * 4;
            float4 a = *(const float4*)(A + (size_t)(m0 + r) * DM + kt + c4);
            As[c4 + 0][r] = a.x; As[c4 + 1][r] = a.y;
            As[c4 + 2][r] = a.z; As[c4 + 3][r] = a.w;
        }
        {
            int n = tid >> 2, c4 = (tid & 3) * 4;
            float4 q4 = *(const float4*)(Bq + (size_t)(n0 + n) * DM + kt + c4);
            Bs[c4 + 0][n] = q4.x; Bs[c4 + 1][n] = q4.y;
            Bs[c4 + 2][n] = q4.z; Bs[c4 + 3][n] = q4.w;
        }
        __syncthreads();
        #pragma unroll
        for (int k = 0; k < BK; k++) {
            float4 a0 = *(const float4*)&As[k][ty * 8];
            float4 a1 = *(const float4*)&As[k][ty * 8 + 4];
            float4 b0 = *(const float4*)&Bs[k][tx * 4];
            float am[8] = {a0.x, a0.y, a0.z, a0.w, a1.x, a1.y, a1.z, a1.w};
            float bn[4] = {b0.x, b0.y, b0.z, b0.w};
            #pragma unroll
            for (int i = 0; i < 8; i++)
                #pragma unroll
                for (int j = 0; j < 4; j++)
                    acc[i][j] += am[i] * bn[j];
        }
        __syncthreads();
    }

    const float NEG_INF = __int_as_float(0xff800000);
    #pragma unroll
    for (int i = 0; i < 8; i++) {
        int t = m0 + ty * 8 + i;
        #pragma unroll
        for (int j = 0; j < 4; j++) {
            int s = n0 + tx * 4 + j;
            C[(size_t)t * TSEQ + s] = (s <= t) ? acc[i][j] : NEG_INF;
        }
    }
}

// ---------------- row softmax over scores (row length 512) ----------------
__global__ void softmax_kernel() {
    size_t row = blockIdx.x;
    float* w = g_scores + row * TSEQ;
    int tid = threadIdx.x;
    float v0 = w[tid], v1 = w[tid + 256];
    __shared__ float sh[256];
    sh[tid] = fmaxf(v0, v1);
    __syncthreads();
    for (int o = 128; o; o >>= 1) {
        if (tid < o) sh[tid] = fmaxf(sh[tid], sh[tid + o]);
        __syncthreads();
    }
    float m = sh[0];
    __syncthreads();
    float e0 = expf(v0 - m), e1 = expf(v1 - m);
    sh[tid] = e0 + e1;
    __syncthreads();
    for (int o = 128; o; o >>= 1) {
        if (tid < o) sh[tid] += sh[tid + o];
        __syncthreads();
    }
    float inv = 1.f / sh[0];
    w[tid] = e0 * inv;
    w[tid + 256] = e1 * inv;
}

// ---------------- attn out: O[z][t,e] = sum_s P[t,s] V[s,e]  (NN, N=64) ----------------
__global__ void __launch_bounds__(256)
attn_av(const float* __restrict__ Vb) {
    int z = blockIdx.z;
    int b = z / NH, h = z % NH;
    const float* A  = g_scores + (size_t)z * TSEQ * TSEQ;        // [T,T]
    const float* Bv = Vb + (size_t)b * TSEQ * DM + h * HDIM;     // B[s*DM + e]
    float* C = g_attn + (size_t)b * TSEQ * DM + h * HDIM;        // C[t*DM + e]

    __shared__ float As[BK][BM];
    __shared__ float Bs[BK][BN];
    int tid = threadIdx.x;
    int tx = tid & 15, ty = tid >> 4;
    int m0 = blockIdx.y * BM;
    float acc[8][4] = {};

    for (int kt = 0; kt < TSEQ; kt += BK) {
        #pragma unroll
        for (int i = 0; i < 2; i++) {
            int v = tid + i * 256;
            int r = v >> 2, c4 = (v & 3) * 4;
            float4 a = *(const float4*)(A + (size_t)(m0 + r) * TSEQ + kt + c4);
            As[c4 + 0][r] = a.x; As[c4 + 1][r] = a.y;
            As[c4 + 2][r] = a.z; As[c4 + 3][r] = a.w;
        }
        #pragma unroll
        for (int j = 0; j < 4; j++) {
            int k = (tid >> 6) + j * 4;
            int n = tid & 63;
            Bs[k][n] = Bv[(size_t)(kt + k) * DM + n];
        }
        __syncthreads();
        #pragma unroll
        for (int k = 0; k < BK; k++) {
            float4 a0 = *(const float4*)&As[k][ty * 8];
            float4 a1 = *(const float4*)&As[k][ty * 8 + 4];
            float4 b0 = *(const float4*)&Bs[k][tx * 4];
            float am[8] = {a0.x, a0.y, a0.z, a0.w, a1.x, a1.y, a1.z, a1.w};
            float bn[4] = {b0.x, b0.y, b0.z, b0.w};
            #pragma unroll
            for (int i = 0; i < 8; i++)
                #pragma unroll
                for (int j = 0; j < 4; j++)
                    acc[i][j] += am[i] * bn[j];
        }
        __syncthreads();
    }

    #pragma unroll
    for (int i = 0; i < 8; i++) {
        int t = m0 + ty * 8 + i;
        #pragma unroll
        for (int j = 0; j < 4; j++)
            C[(size_t)t * DM + tx * 4 + j] = acc[i][j];
    }
}

// ---------------- loss: per-row online logsumexp NLL ----------------
__global__ void loss_kernel(const float* __restrict__ logits,
                            const int* __restrict__ target) {
    int row = blockIdx.x;
    const float* lg = logits + (size_t)row * VCAB;
    int tid = threadIdx.x;
    float m = -FLT_MAX, s = 0.f;
    for (int i = tid; i < VCAB; i += blockDim.x) {
        float v = lg[i];
        if (v > m) { s = s * expf(m - v) + 1.f; m = v; }
        else       { s += expf(v - m); }
    }
    __shared__ float sm[256], ss[256];
    sm[tid] = m; ss[tid] = s;
    __syncthreads();
    for (int o = 128; o; o >>= 1) {
        if (tid < o) {
            float m2 = sm[tid + o], s2 = ss[tid + o];
            float mm = fmaxf(sm[tid], m2);
            ss[tid] = ss[tid] * expf(sm[tid] - mm) + s2 * expf(m2 - mm);
            sm[tid] = mm;
        }
        __syncthreads();
    }
    if (tid == 0) {
        float lse = sm[0] + logf(ss[0]);
        g_nll[row] = lse - lg[target[row]];
    }
}

__global__ void loss_reduce(float* out) {
    __shared__ float sh[256];
    float s = 0.f;
    for (int i = threadIdx.x; i < NTOK; i += 256) s += g_nll[i];
    sh[threadIdx.x] = s;
    __syncthreads();
    for (int o = 128; o; o >>= 1) {
        if (threadIdx.x < o) sh[threadIdx.x] += sh[threadIdx.x + o];
        __syncthreads();
    }
    if (threadIdx.x == 0) out[0] = sh[0] * (1.f / NTOK);
}

// ---------------- host ----------------
extern "C" void kernel_launch(void* const* d_in, const int* in_sizes, int n_in,
                              void* d_out, int out_size) {
    const int*   x_ids      = (const int*)d_in[0];
    const int*   target     = (const int*)d_in[1];
    const float* tok_emb    = (const float*)d_in[2];
    const float* pos_emb    = (const float*)d_in[3];
    const float* in_proj_w  = (const float*)d_in[4];
    const float* in_proj_b  = (const float*)d_in[5];
    const float* wk         = (const float*)d_in[6];
    const float* bk         = (const float*)d_in[7];
    const float* wq         = (const float*)d_in[8];
    const float* bq         = (const float*)d_in[9];
    const float* wv         = (const float*)d_in[10];
    const float* bv         = (const float*)d_in[11];
    const float* out_proj_w = (const float*)d_in[12];
    const float* out_proj_b = (const float*)d_in[13];
    const float* ff_w1      = (const float*)d_in[14];
    const float* ff_b1      = (const float*)d_in[15];
    const float* ff_w2      = (const float*)d_in[16];
    const float* ff_b2      = (const float*)d_in[17];
    const float* lna_g      = (const float*)d_in[18];
    const float* lna_b      = (const float*)d_in[19];
    const float* lnf_g      = (const float*)d_in[20];
    const float* lnf_b      = (const float*)d_in[21];
    const float* out_w      = (const float*)d_in[22];
    const float* out_b      = (const float*)d_in[23];

    float *px, *ph, *ph2, *pq, *pk, *pv, *pattn, *pff, *pwq, *pwk, *pwv, *plog;
    cudaGetSymbolAddress((void**)&px,    g_x);
    cudaGetSymbolAddress((void**)&ph,    g_h);
    cudaGetSymbolAddress((void**)&ph2,   g_h2);
    cudaGetSymbolAddress((void**)&pq,    g_q);
    cudaGetSymbolAddress((void**)&pk,    g_k);
    cudaGetSymbolAddress((void**)&pv,    g_v);
    cudaGetSymbolAddress((void**)&pattn, g_attn);
    cudaGetSymbolAddress((void**)&pff,   g_ff);
    cudaGetSymbolAddress((void**)&pwq,   g_wq);
    cudaGetSymbolAddress((void**)&pwk,   g_wk);
    cudaGetSymbolAddress((void**)&pwv,   g_wv);
    cudaGetSymbolAddress((void**)&plog,  g_logits_scratch);

    const size_t LOGITS_N = (size_t)NTOK * VCAB;
    float* logits = ((size_t)out_size >= LOGITS_N) ? (float*)d_out : plog;

    embed_kernel<<<(NTOK * DM + 255) / 256, 256>>>(x_ids, tok_emb, pos_emb);
    repack_kernel<<<(NL * DM * DM + 255) / 256, 256>>>(wq, wk, wv);

    dim3 blk(256);
    dim3 g_dm(DM / BN, NTOK / BM);          // [2048, 768] GEMMs
    dim3 g_ff1(DFF / BN, NTOK / BM);        // [2048, 3072]
    dim3 g_sc(TSEQ / BN, TSEQ / BM, BBAT * NH);
    dim3 g_av(1, TSEQ / BM, BBAT * NH);

    for (int l = 0; l < NL; l++) {
        ln_kernel<<<NTOK, 256>>>(px, ph, lna_g + l * DM, lna_b + l * DM);
        sgemm_nn<<<g_dm, blk>>>(ph, in_proj_w + (size_t)l * DM * DM, ph2,
                                NTOK, DM, DM, in_proj_b + l * DM, nullptr, 0);
        sgemm_nn<<<g_dm, blk>>>(ph2, pwq + (size_t)l * DM * DM, pq,
                                NTOK, DM, DM, bq + l * DM, nullptr, 0);
        sgemm_nn<<<g_dm, blk>>>(ph2, pwk + (size_t)l * DM * DM, pk,
                                NTOK, DM, DM, bk + l * DM, nullptr, 0);
        sgemm_nn<<<g_dm, blk>>>(ph2, pwv + (size_t)l * DM * DM, pv,
                                NTOK, DM, DM, bv + l * DM, nullptr, 0);
        attn_scores<<<g_sc, blk>>>(pk, pq);
        softmax_kernel<<<BBAT * NH * TSEQ, 256>>>();
        attn_av<<<g_av, blk>>>(pv);
        sgemm_nn<<<g_dm, blk>>>(pattn, out_proj_w + (size_t)l * DM * DM, px,
                                NTOK, DM, DM, out_proj_b + l * DM, px, 0);
        ln_kernel<<<NTOK, 256>>>(px, ph, lnf_g + l * DM, lnf_b + l * DM);
        sgemm_nn<<<g_ff1, blk>>>(ph, ff_w1 + (size_t)l * DM * DFF, pff,
                                 NTOK, DFF, DM, ff_b1 + l * DFF, nullptr, 1);
        sgemm_nn<<<g_dm, blk>>>(pff, ff_w2 + (size_t)l * DFF * DM, px,
                                NTOK, DM, DFF, ff_b2 + l * DM, px, 0);
    }

    // LM head: [2048, 768] @ [768, 50257] + out_b
    dim3 g_lm((VCAB + BN - 1) / BN, NTOK / BM);
    sgemm_nn<<<g_lm, blk>>>(px, out_w, logits, NTOK, VCAB, DM, out_b, nullptr, 0);

    if ((size_t)out_size != LOGITS_N) {
        loss_kernel<<<NTOK, 256>>>(logits, target);
        loss_reduce<<<1, 256>>>((float*)d_out + (out_size - 1));
    }
}

// round 3
// speedup vs baseline: 2.1860x; 2.1860x over previous
#include <cuda_runtime.h>
#include <cuda_bf16.h>
#include <math.h>
#include <float.h>
#include <stdint.h>

// ---------------- model constants ----------------
#define VCAB 50257
#define DM   768
#define NL   6
#define NH   12
#define HDIM 64
#define BBAT 4
#define TSEQ 512
#define NTOK (BBAT * TSEQ)     // 2048
#define DFF  (4 * DM)          // 3072

// ---------------- fp32 scratch ----------------
__device__ float g_x   [NTOK * DM];
__device__ float g_h   [NTOK * DM];
__device__ float g_h2  [NTOK * DM];
__device__ float g_q   [NTOK * DM];
__device__ float g_k   [NTOK * DM];
__device__ float g_v   [NTOK * DM];
__device__ float g_attn[NTOK * DM];
__device__ float g_ff  [NTOK * DFF];
__device__ float g_scores[(size_t)BBAT * NH * TSEQ * TSEQ];
__device__ float g_nll[NTOK];
__device__ float g_logits_scratch[(size_t)NTOK * VCAB];

// ---------------- bf16 split transposed weights [N,K] ----------------
__device__ __nv_bfloat16 g_tq_h[NL * DM * DM],  g_tq_l[NL * DM * DM];
__device__ __nv_bfloat16 g_tk_h[NL * DM * DM],  g_tk_l[NL * DM * DM];
__device__ __nv_bfloat16 g_tv_h[NL * DM * DM],  g_tv_l[NL * DM * DM];
__device__ __nv_bfloat16 g_tin_h[NL * DM * DM], g_tin_l[NL * DM * DM];
__device__ __nv_bfloat16 g_top_h[NL * DM * DM], g_top_l[NL * DM * DM];
__device__ __nv_bfloat16 g_tf1_h[NL * DM * DFF], g_tf1_l[NL * DM * DFF];
__device__ __nv_bfloat16 g_tf2_h[NL * DM * DFF], g_tf2_l[NL * DM * DFF];
__device__ __nv_bfloat16 g_tow_h[(size_t)VCAB * DM], g_tow_l[(size_t)VCAB * DM];

// ---------------- helpers ----------------
static __device__ __forceinline__ uint32_t smem_u32(const void* p) {
    uint32_t a;
    asm("{ .reg .u64 t; cvta.to.shared.u64 t, %1; cvt.u32.u64 %0, t; }"
        : "=r"(a) : "l"(p));
    return a;
}
static __device__ __forceinline__ uint32_t pack2(__nv_bfloat16 a, __nv_bfloat16 b) {
    __nv_bfloat162 t = __halves2bfloat162(a, b);
    return *(uint32_t*)&t;
}
static __device__ __forceinline__ void ldsm4(uint32_t* r, uint32_t addr) {
    asm volatile("ldmatrix.sync.aligned.m8n8.x4.shared.b16 {%0,%1,%2,%3}, [%4];"
                 : "=r"(r[0]), "=r"(r[1]), "=r"(r[2]), "=r"(r[3]) : "r"(addr));
}
static __device__ __forceinline__ void mma_bf16(float* c, const uint32_t* a,
                                                const uint32_t* b) {
    asm volatile(
        "mma.sync.aligned.m16n8k16.row.col.f32.bf16.bf16.f32 "
        "{%0,%1,%2,%3}, {%4,%5,%6,%7}, {%8,%9}, {%0,%1,%2,%3};"
        : "+f"(c[0]), "+f"(c[1]), "+f"(c[2]), "+f"(c[3])
        : "r"(a[0]), "r"(a[1]), "r"(a[2]), "r"(a[3]), "r"(b[0]), "r"(b[1]));
}
// swizzled byte offset within an 8KB [128 rows x 32 bf16] region
static __device__ __forceinline__ uint32_t sw_off(int row, int kchunk) {
    return (uint32_t)(row * 64 + ((kchunk ^ ((row >> 1) & 3)) << 4));
}

// ---------------- embedding ----------------
__global__ void embed_kernel(const int* __restrict__ ids,
                             const float* __restrict__ tok,
                             const float* __restrict__ pos) {
    int i = blockIdx.x * blockDim.x + threadIdx.x;
    if (i >= NTOK * DM) return;
    int row = i / DM, d = i - row * DM;
    int t = row % TSEQ;
    g_x[i] = tok[(size_t)ids[row] * DM + d] + pos[t * DM + d];
}

// ---------------- weight repack: [K,N] fp32 -> [N,K] bf16 hi/lo ----------------
__global__ void repack_t(const float* __restrict__ src,
                         __nv_bfloat16* __restrict__ dh,
                         __nv_bfloat16* __restrict__ dl, int K, int N) {
    __shared__ float t[32][33];
    size_t mo = (size_t)blockIdx.z * K * N;
    int k0 = blockIdx.y * 32, n0 = blockIdx.x * 32;
    int tx = threadIdx.x, ty = threadIdx.y;
    for (int i = ty; i < 32; i += 8) {
        int k = k0 + i, n = n0 + tx;
        t[i][tx] = (k < K && n < N) ? src[mo + (size_t)k * N + n] : 0.f;
    }
    __syncthreads();
    for (int i = ty; i < 32; i += 8) {
        int n = n0 + i, k = k0 + tx;
        if (n < N && k < K) {
            float v = t[tx][i];
            __nv_bfloat16 h = __float2bfloat16(v);
            __nv_bfloat16 l = __float2bfloat16(v - __bfloat162float(h));
            size_t o = mo + (size_t)n * K + k;
            dh[o] = h; dl[o] = l;
        }
    }
}

// qkv: [L,H,D,HD] -> per layer [H*HD, D] bf16 hi/lo (transposed, split)
__global__ void repack_qkv_t(const float* __restrict__ wq,
                             const float* __restrict__ wk,
                             const float* __restrict__ wv) {
    __shared__ float tq[32][33], tk[32][33], tv[32][33];
    int z = blockIdx.z, l = z / NH, h = z % NH;
    int d0 = blockIdx.y * 32, e0 = blockIdx.x * 32;
    int tx = threadIdx.x, ty = threadIdx.y;
    size_t sbo = ((size_t)l * NH + h) * DM * HDIM;
    for (int i = ty; i < 32; i += 8) {
        int d = d0 + i, e = e0 + tx;
        size_t idx = sbo + (size_t)d * HDIM + e;
        tq[i][tx] = wq[idx]; tk[i][tx] = wk[idx]; tv[i][tx] = wv[idx];
    }
    __syncthreads();
    size_t db = (size_t)l * DM * DM;
    for (int i = ty; i < 32; i += 8) {
        int e = e0 + i, d = d0 + tx;
        size_t o = db + (size_t)(h * HDIM + e) * DM + d;
        float v;
        __nv_bfloat16 hh;
        v = tq[tx][i]; hh = __float2bfloat16(v);
        g_tq_h[o] = hh; g_tq_l[o] = __float2bfloat16(v - __bfloat162float(hh));
        v = tk[tx][i]; hh = __float2bfloat16(v);
        g_tk_h[o] = hh; g_tk_l[o] = __float2bfloat16(v - __bfloat162float(hh));
        v = tv[tx][i]; hh = __float2bfloat16(v);
        g_tv_h[o] = hh; g_tv_l[o] = __float2bfloat16(v - __bfloat162float(hh));
    }
}

// ---------------- layernorm ----------------
__global__ void ln_kernel(const float* __restrict__ in, float* __restrict__ out,
                          const float* __restrict__ g, const float* __restrict__ b) {
    int row = blockIdx.x;
    const float* x = in + (size_t)row * DM;
    float s = 0.f, s2 = 0.f;
    for (int i = threadIdx.x; i < DM; i += blockDim.x) {
        float v = x[i];
        s += v; s2 += v * v;
    }
    __shared__ float rs[32], rs2[32];
    for (int o = 16; o; o >>= 1) {
        s  += __shfl_down_sync(0xffffffffu, s, o);
        s2 += __shfl_down_sync(0xffffffffu, s2, o);
    }
    int wid = threadIdx.x >> 5, lid = threadIdx.x & 31;
    if (lid == 0) { rs[wid] = s; rs2[wid] = s2; }
    __syncthreads();
    if (wid == 0) {
        int nw = blockDim.x >> 5;
        s  = (lid < nw) ? rs[lid]  : 0.f;
        s2 = (lid < nw) ? rs2[lid] : 0.f;
        for (int o = 16; o; o >>= 1) {
            s  += __shfl_down_sync(0xffffffffu, s, o);
            s2 += __shfl_down_sync(0xffffffffu, s2, o);
        }
        if (lid == 0) { rs[0] = s; rs2[0] = s2; }
    }
    __syncthreads();
    float mean = rs[0] * (1.f / DM);
    float var  = rs2[0] * (1.f / DM) - mean * mean;
    float inv  = rsqrtf(var + 1e-5f);
    float* o = out + (size_t)row * DM;
    for (int i = threadIdx.x; i < DM; i += blockDim.x)
        o[i] = (x[i] - mean) * inv * g[i] + b[i];
}

// ---------------- HMMA bf16-split GEMM ----------------
// C[M,N] = A[M,K] @ W[K,N] via Ah*Bh + Ah*Bl + Al*Bh.
// A fp32 [M,K]; Bh/Bl bf16 [N,K]. grid=(M/128, ceil(N/128)), 256 thr.
// SMEM stage (32KB): [Ah 8K][Al 8K][Bh 8K][Bl 8K], each 128rows x 32 bf16 swizzled.
#define GBM 128
#define GBN 128
#define STG 32768
#define SM_DYN (2 * STG)

__global__ void __launch_bounds__(256)
gemm_mma(const float* __restrict__ A, const __nv_bfloat16* __restrict__ Bh,
         const __nv_bfloat16* __restrict__ Bl, float* __restrict__ C,
         int N, int K, const float* __restrict__ bias,
         const float* __restrict__ res, int relu) {
    extern __shared__ char smem[];
    const uint32_t sb = smem_u32(smem);
    const int tid = threadIdx.x;
    const int lane = tid & 31;
    const int w = tid >> 5;
    const int wm = (w & 1) * 64;       // warp row offset in tile
    const int wn = (w >> 1) * 32;      // warp col offset in tile
    const int m0 = blockIdx.x * GBM;
    const int n0 = blockIdx.y * GBN;
    const int NK = K >> 5;

    float acc[4][4][4];
    #pragma unroll
    for (int i = 0; i < 4; i++)
        #pragma unroll
        for (int j = 0; j < 4; j++)
            #pragma unroll
            for (int e = 0; e < 4; e++) acc[i][j][e] = 0.f;

    float4 ar[4];
    uint4  brh[2], brl[2];

    // -------- staging helpers as macros --------
#define LOADG(IT) do {                                                        \
        int kt = (IT) << 5;                                                   \
        _Pragma("unroll")                                                     \
        for (int i = 0; i < 4; i++) {                                         \
            int idx = tid + (i << 8);                                         \
            int row = idx >> 3, kq = idx & 7;                                 \
            ar[i] = *(const float4*)(A + (size_t)(m0 + row) * K + kt + (kq << 2)); \
        }                                                                     \
        _Pragma("unroll")                                                     \
        for (int i = 0; i < 2; i++) {                                         \
            int idx = tid + (i << 8);                                         \
            int row = idx >> 2, kq = idx & 3;                                 \
            int n = n0 + row;                                                 \
            if (n < N) {                                                      \
                size_t go = (size_t)n * K + kt + (kq << 3);                   \
                brh[i] = *(const uint4*)(Bh + go);                            \
                brl[i] = *(const uint4*)(Bl + go);                            \
            } else {                                                          \
                brh[i] = make_uint4(0, 0, 0, 0);                              \
                brl[i] = make_uint4(0, 0, 0, 0);                              \
            }                                                                 \
        }                                                                     \
    } while (0)

#define STORES(BUF) do {                                                      \
        char* st = smem + (BUF) * STG;                                        \
        _Pragma("unroll")                                                     \
        for (int i = 0; i < 4; i++) {                                         \
            int idx = tid + (i << 8);                                         \
            int row = idx >> 3, kq = idx & 7;                                 \
            float4 a = ar[i];                                                 \
            __nv_bfloat16 hx = __float2bfloat16(a.x);                         \
            __nv_bfloat16 hy = __float2bfloat16(a.y);                         \
            __nv_bfloat16 hz = __float2bfloat16(a.z);                         \
            __nv_bfloat16 hw = __float2bfloat16(a.w);                         \
            __nv_bfloat16 lx = __float2bfloat16(a.x - __bfloat162float(hx));  \
            __nv_bfloat16 ly = __float2bfloat16(a.y - __bfloat162float(hy));  \
            __nv_bfloat16 lz = __float2bfloat16(a.z - __bfloat162float(hz));  \
            __nv_bfloat16 lw = __float2bfloat16(a.w - __bfloat162float(hw));  \
            uint2 hv, lv;                                                     \
            hv.x = pack2(hx, hy); hv.y = pack2(hz, hw);                       \
            lv.x = pack2(lx, ly); lv.y = pack2(lz, lw);                       \
            uint32_t off = sw_off(row, kq >> 1) + ((kq & 1) << 3);            \
            *(uint2*)(st + off)        = hv;                                  \
            *(uint2*)(st + 8192 + off) = lv;                                  \
        }                                                                     \
        _Pragma("unroll")                                                     \
        for (int i = 0; i < 2; i++) {                                         \
            int idx = tid + (i << 8);                                         \
            int row = idx >> 2, kq = idx & 3;                                 \
            uint32_t off = sw_off(row, kq);                                   \
            *(uint4*)(st + 16384 + off) = brh[i];                             \
            *(uint4*)(st + 24576 + off) = brl[i];                             \
        }                                                                     \
    } while (0)

    LOADG(0);
    STORES(0);
    __syncthreads();

    const int r8  = lane & 7;
    const int oct = lane >> 3;

    for (int it = 0; it < NK; it++) {
        const int buf = it & 1;
        const bool hn = (it + 1) < NK;
        if (hn) LOADG(it + 1);

        const uint32_t base = sb + buf * STG;
        #pragma unroll
        for (int ks = 0; ks < 2; ks++) {
            uint32_t bH[4][2], bL[4][2], aF[4][4];
            // B frags: 2 ldmatrix.x4 per matrix cover 4 n-tiles
            #pragma unroll
            for (int p = 0; p < 2; p++) {
                int n = wn + p * 16 + (oct >> 1) * 8 + r8;
                int kc = ks * 2 + (oct & 1);
                uint32_t ad = base + 16384 + sw_off(n, kc);
                uint32_t t[4];
                ldsm4(t, ad);
                bH[p * 2][0] = t[0]; bH[p * 2][1] = t[1];
                bH[p * 2 + 1][0] = t[2]; bH[p * 2 + 1][1] = t[3];
                ldsm4(t, ad + 8192);
                bL[p * 2][0] = t[0]; bL[p * 2][1] = t[1];
                bL[p * 2 + 1][0] = t[2]; bL[p * 2 + 1][1] = t[3];
            }
            // A hi frags
            #pragma unroll
            for (int mt = 0; mt < 4; mt++) {
                int row = wm + mt * 16 + (oct & 1) * 8 + r8;
                int kc = ks * 2 + (oct >> 1);
                ldsm4(aF[mt], base + sw_off(row, kc));
            }
            #pragma unroll
            for (int mt = 0; mt < 4; mt++)
                #pragma unroll
                for (int nt = 0; nt < 4; nt++) {
                    mma_bf16(acc[mt][nt], aF[mt], bH[nt]);
                    mma_bf16(acc[mt][nt], aF[mt], bL[nt]);
                }
            // A lo frags (reuse regs)
            #pragma unroll
            for (int mt = 0; mt < 4; mt++) {
                int row = wm + mt * 16 + (oct & 1) * 8 + r8;
                int kc = ks * 2 + (oct >> 1);
                ldsm4(aF[mt], base + 8192 + sw_off(row, kc));
            }
            #pragma unroll
            for (int mt = 0; mt < 4; mt++)
                #pragma unroll
                for (int nt = 0; nt < 4; nt++)
                    mma_bf16(acc[mt][nt], aF[mt], bH[nt]);
        }

        if (hn) STORES(buf ^ 1);
        __syncthreads();
    }

    // -------- epilogue --------
    const int g2 = lane >> 2;
    const int t2 = (lane & 3) * 2;
    const bool fast = (n0 + GBN <= N) && ((N & 1) == 0);

    #pragma unroll
    for (int mt = 0; mt < 4; mt++) {
        #pragma unroll
        for (int nt = 0; nt < 4; nt++) {
            float* c = acc[mt][nt];
            int row = m0 + wm + mt * 16 + g2;
            int col = n0 + wn + nt * 8 + t2;
            if (fast) {
                float2 v0 = make_float2(c[0], c[1]);
                float2 v1 = make_float2(c[2], c[3]);
                if (bias) {
                    float2 bb = *(const float2*)(bias + col);
                    v0.x += bb.x; v0.y += bb.y; v1.x += bb.x; v1.y += bb.y;
                }
                if (res) {
                    float2 r0 = *(const float2*)(res + (size_t)row * N + col);
                    float2 r1 = *(const float2*)(res + (size_t)(row + 8) * N + col);
                    v0.x += r0.x; v0.y += r0.y; v1.x += r1.x; v1.y += r1.y;
                }
                if (relu) {
                    v0.x = fmaxf(v0.x, 0.f); v0.y = fmaxf(v0.y, 0.f);
                    v1.x = fmaxf(v1.x, 0.f); v1.y = fmaxf(v1.y, 0.f);
                }
                *(float2*)(C + (size_t)row * N + col) = v0;
                *(float2*)(C + (size_t)(row + 8) * N + col) = v1;
            } else {
                #pragma unroll
                for (int e = 0; e < 2; e++) {
                    int nn = col + e;
                    if (nn < N) {
                        float v0 = c[e], v1 = c[2 + e];
                        if (bias) { float bb = bias[nn]; v0 += bb; v1 += bb; }
                        if (res) {
                            v0 += res[(size_t)row * N + nn];
                            v1 += res[(size_t)(row + 8) * N + nn];
                        }
                        if (relu) { v0 = fmaxf(v0, 0.f); v1 = fmaxf(v1, 0.f); }
                        C[(size_t)row * N + nn] = v0;
                        C[(size_t)(row + 8) * N + nn] = v1;
                    }
                }
            }
        }
    }
#undef LOADG
#undef STORES
}

// ---------------- attention (fp32 SIMT) ----------------
#define BM 128
#define BN 64
#define BK 16

__global__ void __launch_bounds__(256)
attn_scores(const float* __restrict__ Kb, const float* __restrict__ Qb) {
    int z = blockIdx.z;
    int b = z / NH, h = z % NH;
    const float* A  = Kb + (size_t)b * TSEQ * DM + h * HDIM;
    const float* Bq = Qb + (size_t)b * TSEQ * DM + h * HDIM;
    float* C = g_scores + (size_t)z * TSEQ * TSEQ;

    __shared__ float As[BK][BM];
    __shared__ float Bs[BK][BN];
    int tid = threadIdx.x;
    int tx = tid & 15, ty = tid >> 4;
    int m0 = blockIdx.y * BM, n0 = blockIdx.x * BN;
    float acc[8][4] = {};

    for (int kt = 0; kt < HDIM; kt += BK) {
        #pragma unroll
        for (int i = 0; i < 2; i++) {
            int v = tid + i * 256;
            int r = v >> 2, c4 = (v & 3) * 4;
            float4 a = *(const float4*)(A + (size_t)(m0 + r) * DM + kt + c4);
            As[c4 + 0][r] = a.x; As[c4 + 1][r] = a.y;
            As[c4 + 2][r] = a.z; As[c4 + 3][r] = a.w;
        }
        {
            int n = tid >> 2, c4 = (tid & 3) * 4;
            float4 q4 = *(const float4*)(Bq + (size_t)(n0 + n) * DM + kt + c4);
            Bs[c4 + 0][n] = q4.x; Bs[c4 + 1][n] = q4.y;
            Bs[c4 + 2][n] = q4.z; Bs[c4 + 3][n] = q4.w;
        }
        __syncthreads();
        #pragma unroll
        for (int k = 0; k < BK; k++) {
            float4 a0 = *(const float4*)&As[k][ty * 8];
            float4 a1 = *(const float4*)&As[k][ty * 8 + 4];
            float4 b0 = *(const float4*)&Bs[k][tx * 4];
            float am[8] = {a0.x, a0.y, a0.z, a0.w, a1.x, a1.y, a1.z, a1.w};
            float bn[4] = {b0.x, b0.y, b0.z, b0.w};
            #pragma unroll
            for (int i = 0; i < 8; i++)
                #pragma unroll
                for (int j = 0; j < 4; j++)
                    acc[i][j] += am[i] * bn[j];
        }
        __syncthreads();
    }

    const float NEG_INF = __int_as_float(0xff800000);
    #pragma unroll
    for (int i = 0; i < 8; i++) {
        int t = m0 + ty * 8 + i;
        #pragma unroll
        for (int j = 0; j < 4; j++) {
            int s = n0 + tx * 4 + j;
            C[(size_t)t * TSEQ + s] = (s <= t) ? acc[i][j] : NEG_INF;
        }
    }
}

__global__ void softmax_kernel() {
    size_t row = blockIdx.x;
    float* w = g_scores + row * TSEQ;
    int tid = threadIdx.x;
    float v0 = w[tid], v1 = w[tid + 256];
    __shared__ float sh[256];
    sh[tid] = fmaxf(v0, v1);
    __syncthreads();
    for (int o = 128; o; o >>= 1) {
        if (tid < o) sh[tid] = fmaxf(sh[tid], sh[tid + o]);
        __syncthreads();
    }
    float m = sh[0];
    __syncthreads();
    float e0 = expf(v0 - m), e1 = expf(v1 - m);
    sh[tid] = e0 + e1;
    __syncthreads();
    for (int o = 128; o; o >>= 1) {
        if (tid < o) sh[tid] += sh[tid + o];
        __syncthreads();
    }
    float inv = 1.f / sh[0];
    w[tid] = e0 * inv;
    w[tid + 256] = e1 * inv;
}

__global__ void __launch_bounds__(256)
attn_av(const float* __restrict__ Vb) {
    int z = blockIdx.z;
    int b = z / NH, h = z % NH;
    const float* A  = g_scores + (size_t)z * TSEQ * TSEQ;
    const float* Bv = Vb + (size_t)b * TSEQ * DM + h * HDIM;
    float* C = g_attn + (size_t)b * TSEQ * DM + h * HDIM;

    __shared__ float As[BK][BM];
    __shared__ float Bs[BK][BN];
    int tid = threadIdx.x;
    int tx = tid & 15, ty = tid >> 4;
    int m0 = blockIdx.y * BM;
    float acc[8][4] = {};

    for (int kt = 0; kt < TSEQ; kt += BK) {
        #pragma unroll
        for (int i = 0; i < 2; i++) {
            int v = tid + i * 256;
            int r = v >> 2, c4 = (v & 3) * 4;
            float4 a = *(const float4*)(A + (size_t)(m0 + r) * TSEQ + kt + c4);
            As[c4 + 0][r] = a.x; As[c4 + 1][r] = a.y;
            As[c4 + 2][r] = a.z; As[c4 + 3][r] = a.w;
        }
        #pragma unroll
        for (int j = 0; j < 4; j++) {
            int k = (tid >> 6) + j * 4;
            int n = tid & 63;
            Bs[k][n] = Bv[(size_t)(kt + k) * DM + n];
        }
        __syncthreads();
        #pragma unroll
        for (int k = 0; k < BK; k++) {
            float4 a0 = *(const float4*)&As[k][ty * 8];
            float4 a1 = *(const float4*)&As[k][ty * 8 + 4];
            float4 b0 = *(const float4*)&Bs[k][tx * 4];
            float am[8] = {a0.x, a0.y, a0.z, a0.w, a1.x, a1.y, a1.z, a1.w};
            float bn[4] = {b0.x, b0.y, b0.z, b0.w};
            #pragma unroll
            for (int i = 0; i < 8; i++)
                #pragma unroll
                for (int j = 0; j < 4; j++)
                    acc[i][j] += am[i] * bn[j];
        }
        __syncthreads();
    }

    #pragma unroll
    for (int i = 0; i < 8; i++) {
        int t = m0 + ty * 8 + i;
        #pragma unroll
        for (int j = 0; j < 4; j++)
            C[(size_t)t * DM + tx * 4 + j] = acc[i][j];
    }
}

// ---------------- loss ----------------
__global__ void loss_kernel(const float* __restrict__ logits,
                            const int* __restrict__ target) {
    int row = blockIdx.x;
    const float* lg = logits + (size_t)row * VCAB;
    int tid = threadIdx.x;
    float m = -FLT_MAX, s = 0.f;
    for (int i = tid; i < VCAB; i += blockDim.x) {
        float v = lg[i];
        if (v > m) { s = s * expf(m - v) + 1.f; m = v; }
        else       { s += expf(v - m); }
    }
    __shared__ float sm[256], ss[256];
    sm[tid] = m; ss[tid] = s;
    __syncthreads();
    for (int o = 128; o; o >>= 1) {
        if (tid < o) {
            float m2 = sm[tid + o], s2 = ss[tid + o];
            float mm = fmaxf(sm[tid], m2);
            ss[tid] = ss[tid] * expf(sm[tid] - mm) + s2 * expf(m2 - mm);
            sm[tid] = mm;
        }
        __syncthreads();
    }
    if (tid == 0) {
        float lse = sm[0] + logf(ss[0]);
        g_nll[row] = lse - lg[target[row]];
    }
}

__global__ void loss_reduce(float* out) {
    __shared__ float sh[256];
    float s = 0.f;
    for (int i = threadIdx.x; i < NTOK; i += 256) s += g_nll[i];
    sh[threadIdx.x] = s;
    __syncthreads();
    for (int o = 128; o; o >>= 1) {
        if (threadIdx.x < o) sh[threadIdx.x] += sh[threadIdx.x + o];
        __syncthreads();
    }
    if (threadIdx.x == 0) out[0] = sh[0] * (1.f / NTOK);
}

// ---------------- host ----------------
extern "C" void kernel_launch(void* const* d_in, const int* in_sizes, int n_in,
                              void* d_out, int out_size) {
    const int*   x_ids      = (const int*)d_in[0];
    const int*   target     = (const int*)d_in[1];
    const float* tok_emb    = (const float*)d_in[2];
    const float* pos_emb    = (const float*)d_in[3];
    const float* in_proj_w  = (const float*)d_in[4];
    const float* in_proj_b  = (const float*)d_in[5];
    const float* wk         = (const float*)d_in[6];
    const float* bk         = (const float*)d_in[7];
    const float* wq         = (const float*)d_in[8];
    const float* bq         = (const float*)d_in[9];
    const float* wv         = (const float*)d_in[10];
    const float* bv         = (const float*)d_in[11];
    const float* out_proj_w = (const float*)d_in[12];
    const float* out_proj_b = (const float*)d_in[13];
    const float* ff_w1      = (const float*)d_in[14];
    const float* ff_b1      = (const float*)d_in[15];
    const float* ff_w2      = (const float*)d_in[16];
    const float* ff_b2      = (const float*)d_in[17];
    const float* lna_g      = (const float*)d_in[18];
    const float* lna_b      = (const float*)d_in[19];
    const float* lnf_g      = (const float*)d_in[20];
    const float* lnf_b      = (const float*)d_in[21];
    const float* out_w      = (const float*)d_in[22];
    const float* out_b      = (const float*)d_in[23];

    float *px, *ph, *ph2, *pq, *pk, *pv, *pattn, *pff, *plog;
    cudaGetSymbolAddress((void**)&px,    g_x);
    cudaGetSymbolAddress((void**)&ph,    g_h);
    cudaGetSymbolAddress((void**)&ph2,   g_h2);
    cudaGetSymbolAddress((void**)&pq,    g_q);
    cudaGetSymbolAddress((void**)&pk,    g_k);
    cudaGetSymbolAddress((void**)&pv,    g_v);
    cudaGetSymbolAddress((void**)&pattn, g_attn);
    cudaGetSymbolAddress((void**)&pff,   g_ff);
    cudaGetSymbolAddress((void**)&plog,  g_logits_scratch);

    __nv_bfloat16 *tq_h, *tq_l, *tk_h, *tk_l, *tv_h, *tv_l;
    __nv_bfloat16 *tin_h, *tin_l, *top_h, *top_l;
    __nv_bfloat16 *tf1_h, *tf1_l, *tf2_h, *tf2_l, *tow_h, *tow_l;
    cudaGetSymbolAddress((void**)&tq_h,  g_tq_h);  cudaGetSymbolAddress((void**)&tq_l,  g_tq_l);
    cudaGetSymbolAddress((void**)&tk_h,  g_tk_h);  cudaGetSymbolAddress((void**)&tk_l,  g_tk_l);
    cudaGetSymbolAddress((void**)&tv_h,  g_tv_h);  cudaGetSymbolAddress((void**)&tv_l,  g_tv_l);
    cudaGetSymbolAddress((void**)&tin_h, g_tin_h); cudaGetSymbolAddress((void**)&tin_l, g_tin_l);
    cudaGetSymbolAddress((void**)&top_h, g_top_h); cudaGetSymbolAddress((void**)&top_l, g_top_l);
    cudaGetSymbolAddress((void**)&tf1_h, g_tf1_h); cudaGetSymbolAddress((void**)&tf1_l, g_tf1_l);
    cudaGetSymbolAddress((void**)&tf2_h, g_tf2_h); cudaGetSymbolAddress((void**)&tf2_l, g_tf2_l);
    cudaGetSymbolAddress((void**)&tow_h, g_tow_h); cudaGetSymbolAddress((void**)&tow_l, g_tow_l);

    cudaFuncSetAttribute(gemm_mma, cudaFuncAttributeMaxDynamicSharedMemorySize, SM_DYN);

    const size_t LOGITS_N = (size_t)NTOK * VCAB;
    float* logits = ((size_t)out_size >= LOGITS_N) ? (float*)d_out : plog;

    embed_kernel<<<(NTOK * DM + 255) / 256, 256>>>(x_ids, tok_emb, pos_emb);

    dim3 tb(32, 8);
    repack_qkv_t<<<dim3(2, 24, NL * NH), tb>>>(wq, wk, wv);
    repack_t<<<dim3(24, 24, NL), tb>>>(in_proj_w,  tin_h, tin_l, DM, DM);
    repack_t<<<dim3(24, 24, NL), tb>>>(out_proj_w, top_h, top_l, DM, DM);
    repack_t<<<dim3(96, 24, NL), tb>>>(ff_w1, tf1_h, tf1_l, DM, DFF);
    repack_t<<<dim3(24, 96, NL), tb>>>(ff_w2, tf2_h, tf2_l, DFF, DM);
    repack_t<<<dim3((VCAB + 31) / 32, 24, 1), tb>>>(out_w, tow_h, tow_l, DM, VCAB);

    dim3 blk(256);
    dim3 g_dm(NTOK / GBM, DM / GBN);                  // (16, 6)
    dim3 g_ff1(NTOK / GBM, DFF / GBN);                // (16, 24)
    dim3 g_lm(NTOK / GBM, (VCAB + GBN - 1) / GBN);    // (16, 393)
    dim3 g_sc(TSEQ / BN, TSEQ / BM, BBAT * NH);
    dim3 g_av(1, TSEQ / BM, BBAT * NH);

    for (int l = 0; l < NL; l++) {
        size_t wd = (size_t)l * DM * DM;
        size_t wf = (size_t)l * DM * DFF;
        ln_kernel<<<NTOK, 256>>>(px, ph, lna_g + l * DM, lna_b + l * DM);
        gemm_mma<<<g_dm, blk, SM_DYN>>>(ph, tin_h + wd, tin_l + wd, ph2,
                                        DM, DM, in_proj_b + l * DM, nullptr, 0);
        gemm_mma<<<g_dm, blk, SM_DYN>>>(ph2, tq_h + wd, tq_l + wd, pq,
                                        DM, DM, bq + l * DM, nullptr, 0);
        gemm_mma<<<g_dm, blk, SM_DYN>>>(ph2, tk_h + wd, tk_l + wd, pk,
                                        DM, DM, bk + l * DM, nullptr, 0);
        gemm_mma<<<g_dm, blk, SM_DYN>>>(ph2, tv_h + wd, tv_l + wd, pv,
                                        DM, DM, bv + l * DM, nullptr, 0);
        attn_scores<<<g_sc, blk>>>(pk, pq);
        softmax_kernel<<<BBAT * NH * TSEQ, 256>>>();
        attn_av<<<g_av, blk>>>(pv);
        gemm_mma<<<g_dm, blk, SM_DYN>>>(pattn, top_h + wd, top_l + wd, px,
                                        DM, DM, out_proj_b + l * DM, px, 0);
        ln_kernel<<<NTOK, 256>>>(px, ph, lnf_g + l * DM, lnf_b + l * DM);
        gemm_mma<<<g_ff1, blk, SM_DYN>>>(ph, tf1_h + wf, tf1_l + wf, pff,
                                         DFF, DM, ff_b1 + l * DFF, nullptr, 1);
        gemm_mma<<<g_dm, blk, SM_DYN>>>(pff, tf2_h + wf, tf2_l + wf, px,
                                        DM, DFF, ff_b2 + l * DM, px, 0);
    }

    gemm_mma<<<g_lm, blk, SM_DYN>>>(px, tow_h, tow_l, logits,
                                    VCAB, DM, out_b, nullptr, 0);

    if ((size_t)out_size != LOGITS_N) {
        loss_kernel<<<NTOK, 256>>>(logits, target);
        loss_reduce<<<1, 256>>>((float*)d_out + (out_size - 1));
    }
}

// round 4
// speedup vs baseline: 2.6030x; 1.1908x over previous
#include <cuda_runtime.h>
#include <cuda_bf16.h>
#include <math.h>
#include <float.h>
#include <stdint.h>

// ---------------- model constants ----------------
#define VCAB 50257
#define DM   768
#define NL   6
#define NH   12
#define HDIM 64
#define BBAT 4
#define TSEQ 512
#define NTOK (BBAT * TSEQ)     // 2048
#define DFF  (4 * DM)          // 3072
#define QKVW (3 * DM)          // 2304

// ---------------- scratch ----------------
__device__ float g_x[NTOK * DM];                       // residual stream (fp32)
__device__ float g_qkv[(size_t)NTOK * QKVW];           // fused q|k|v
__device__ float g_scores[(size_t)BBAT * NH * TSEQ * TSEQ];
__device__ float g_nll[NTOK];
__device__ float g_logits_scratch[(size_t)NTOK * VCAB];

// split bf16 activations (hi/lo)
__device__ __nv_bfloat16 g_ah[NTOK * DM],  g_al[NTOK * DM];    // LN out / LM-head in
__device__ __nv_bfloat16 g_h2h[NTOK * DM], g_h2l[NTOK * DM];   // in_proj out
__device__ __nv_bfloat16 g_ath[NTOK * DM], g_atl[NTOK * DM];   // attn out
__device__ __nv_bfloat16 g_ffh[NTOK * DFF], g_ffl[NTOK * DFF]; // ff1 out

// split bf16 transposed weights [N,K]
__device__ __nv_bfloat16 g_tqkv_h[(size_t)NL * QKVW * DM], g_tqkv_l[(size_t)NL * QKVW * DM];
__device__ __nv_bfloat16 g_tin_h[NL * DM * DM], g_tin_l[NL * DM * DM];
__device__ __nv_bfloat16 g_top_h[NL * DM * DM], g_top_l[NL * DM * DM];
__device__ __nv_bfloat16 g_tf1_h[NL * DM * DFF], g_tf1_l[NL * DM * DFF];
__device__ __nv_bfloat16 g_tf2_h[NL * DM * DFF], g_tf2_l[NL * DM * DFF];
__device__ __nv_bfloat16 g_tow_h[(size_t)VCAB * DM], g_tow_l[(size_t)VCAB * DM];
__device__ float g_bqkv[NL * QKVW];

// ---------------- helpers ----------------
static __device__ __forceinline__ uint32_t smem_u32(const void* p) {
    uint32_t a;
    asm("{ .reg .u64 t; cvta.to.shared.u64 t, %1; cvt.u32.u64 %0, t; }"
        : "=r"(a) : "l"(p));
    return a;
}
static __device__ __forceinline__ void ldsm4(uint32_t* r, uint32_t addr) {
    asm volatile("ldmatrix.sync.aligned.m8n8.x4.shared.b16 {%0,%1,%2,%3}, [%4];"
                 : "=r"(r[0]), "=r"(r[1]), "=r"(r[2]), "=r"(r[3]) : "r"(addr));
}
static __device__ __forceinline__ void mma_bf16(float* c, const uint32_t* a,
                                                const uint32_t* b) {
    asm volatile(
        "mma.sync.aligned.m16n8k16.row.col.f32.bf16.bf16.f32 "
        "{%0,%1,%2,%3}, {%4,%5,%6,%7}, {%8,%9}, {%0,%1,%2,%3};"
        : "+f"(c[0]), "+f"(c[1]), "+f"(c[2]), "+f"(c[3])
        : "r"(a[0]), "r"(a[1]), "r"(a[2]), "r"(a[3]), "r"(b[0]), "r"(b[1]));
}
static __device__ __forceinline__ void cpa(uint32_t dst, const void* src) {
    asm volatile("cp.async.cg.shared.global [%0], [%1], 16;" :: "r"(dst), "l"(src));
}
// swizzled byte offset within an 8KB [128 rows x 32 bf16] region
static __device__ __forceinline__ uint32_t sw_off(int row, int kchunk) {
    return (uint32_t)(row * 64 + ((kchunk ^ ((row >> 1) & 3)) << 4));
}
static __device__ __forceinline__ void split1(float v, __nv_bfloat16& h,
                                              __nv_bfloat16& l) {
    h = __float2bfloat16(v);
    l = __float2bfloat16(v - __bfloat162float(h));
}

// ---------------- embedding ----------------
__global__ void embed_kernel(const int* __restrict__ ids,
                             const float* __restrict__ tok,
                             const float* __restrict__ pos) {
    int i = blockIdx.x * blockDim.x + threadIdx.x;
    if (i >= NTOK * DM) return;
    int row = i / DM, d = i - row * DM;
    int t = row % TSEQ;
    g_x[i] = tok[(size_t)ids[row] * DM + d] + pos[t * DM + d];
}

// ---------------- weight repack: [K,N] fp32 -> [N,K] bf16 hi/lo ----------------
__global__ void repack_t(const float* __restrict__ src,
                         __nv_bfloat16* __restrict__ dh,
                         __nv_bfloat16* __restrict__ dl, int K, int N) {
    __shared__ float t[32][33];
    size_t mo = (size_t)blockIdx.z * K * N;
    int k0 = blockIdx.y * 32, n0 = blockIdx.x * 32;
    int tx = threadIdx.x, ty = threadIdx.y;
    for (int i = ty; i < 32; i += 8) {
        int k = k0 + i, n = n0 + tx;
        t[i][tx] = (k < K && n < N) ? src[mo + (size_t)k * N + n] : 0.f;
    }
    __syncthreads();
    for (int i = ty; i < 32; i += 8) {
        int n = n0 + i, k = k0 + tx;
        if (n < N && k < K) {
            __nv_bfloat16 h, l;
            split1(t[tx][i], h, l);
            size_t o = mo + (size_t)n * K + k;
            dh[o] = h; dl[o] = l;
        }
    }
}

// qkv: [L,H,D,HD] -> per layer combined [q|k|v][2304, 768] bf16 hi/lo
__global__ void repack_qkv_t(const float* __restrict__ wq,
                             const float* __restrict__ wk,
                             const float* __restrict__ wv) {
    __shared__ float tq[32][33], tk[32][33], tv[32][33];
    int z = blockIdx.z, l = z / NH, h = z % NH;
    int d0 = blockIdx.y * 32, e0 = blockIdx.x * 32;
    int tx = threadIdx.x, ty = threadIdx.y;
    size_t sbo = ((size_t)l * NH + h) * DM * HDIM;
    for (int i = ty; i < 32; i += 8) {
        int d = d0 + i, e = e0 + tx;
        size_t idx = sbo + (size_t)d * HDIM + e;
        tq[i][tx] = wq[idx]; tk[i][tx] = wk[idx]; tv[i][tx] = wv[idx];
    }
    __syncthreads();
    size_t db = (size_t)l * QKVW * DM;
    for (int i = ty; i < 32; i += 8) {
        int e = e0 + i, d = d0 + tx;
        int nq = h * HDIM + e;
        __nv_bfloat16 hh, ll;
        size_t o;
        o = db + (size_t)nq * DM + d;
        split1(tq[tx][i], hh, ll); g_tqkv_h[o] = hh; g_tqkv_l[o] = ll;
        o = db + (size_t)(DM + nq) * DM + d;
        split1(tk[tx][i], hh, ll); g_tqkv_h[o] = hh; g_tqkv_l[o] = ll;
        o = db + (size_t)(2 * DM + nq) * DM + d;
        split1(tv[tx][i], hh, ll); g_tqkv_h[o] = hh; g_tqkv_l[o] = ll;
    }
}

__global__ void bias_concat(const float* __restrict__ bq,
                            const float* __restrict__ bk,
                            const float* __restrict__ bv) {
    int i = blockIdx.x * blockDim.x + threadIdx.x;
    if (i >= NL * QKVW) return;
    int l = i / QKVW, c = i % QKVW;
    float v = (c < DM) ? bq[l * DM + c]
            : (c < 2 * DM) ? bk[l * DM + c - DM]
            : bv[l * DM + c - 2 * DM];
    g_bqkv[i] = v;
}

// ---------------- layernorm: fp32 in -> split bf16 out ----------------
__global__ void ln_kernel(const float* __restrict__ in,
                          __nv_bfloat16* __restrict__ oh,
                          __nv_bfloat16* __restrict__ ol,
                          const float* __restrict__ g, const float* __restrict__ b) {
    int row = blockIdx.x;
    const float* x = in + (size_t)row * DM;
    float s = 0.f, s2 = 0.f;
    for (int i = threadIdx.x; i < DM; i += blockDim.x) {
        float v = x[i];
        s += v; s2 += v * v;
    }
    __shared__ float rs[32], rs2[32];
    for (int o = 16; o; o >>= 1) {
        s  += __shfl_down_sync(0xffffffffu, s, o);
        s2 += __shfl_down_sync(0xffffffffu, s2, o);
    }
    int wid = threadIdx.x >> 5, lid = threadIdx.x & 31;
    if (lid == 0) { rs[wid] = s; rs2[wid] = s2; }
    __syncthreads();
    if (wid == 0) {
        int nw = blockDim.x >> 5;
        s  = (lid < nw) ? rs[lid]  : 0.f;
        s2 = (lid < nw) ? rs2[lid] : 0.f;
        for (int o = 16; o; o >>= 1) {
            s  += __shfl_down_sync(0xffffffffu, s, o);
            s2 += __shfl_down_sync(0xffffffffu, s2, o);
        }
        if (lid == 0) { rs[0] = s; rs2[0] = s2; }
    }
    __syncthreads();
    float mean = rs[0] * (1.f / DM);
    float var  = rs2[0] * (1.f / DM) - mean * mean;
    float inv  = rsqrtf(var + 1e-5f);
    for (int i = threadIdx.x; i < DM; i += blockDim.x) {
        float v = (x[i] - mean) * inv * g[i] + b[i];
        __nv_bfloat16 h, l;
        split1(v, h, l);
        oh[(size_t)row * DM + i] = h;
        ol[(size_t)row * DM + i] = l;
    }
}

// ---------------- split fp32 activation -> bf16 hi/lo ----------------
__global__ void split_act(const float* __restrict__ x,
                          __nv_bfloat16* __restrict__ oh,
                          __nv_bfloat16* __restrict__ ol, int n) {
    int i = blockIdx.x * blockDim.x + threadIdx.x;
    if (i >= n) return;
    __nv_bfloat16 h, l;
    split1(x[i], h, l);
    oh[i] = h; ol[i] = l;
}

// ---------------- HMMA bf16-split GEMM, cp.async pipelined ----------------
// C[M,N] = A @ W via Ah*Bh + Ah*Bl + Al*Bh. A pre-split bf16 [M,K]; B [N,K].
// Output: fp32 C (bias/res/relu) OR split bf16 Ch/Cl (bias/relu).
// grid=(M/128, ceil(N/128)), 256 threads. SMEM: 2 stages x 32KB.
#define GBM 128
#define GBN 128
#define STG 32768
#define SM_DYN (2 * STG)

__global__ void __launch_bounds__(256, 2)
gemm_mma(const __nv_bfloat16* __restrict__ Ah, const __nv_bfloat16* __restrict__ Al,
         const __nv_bfloat16* __restrict__ Bh, const __nv_bfloat16* __restrict__ Bl,
         float* __restrict__ C, __nv_bfloat16* __restrict__ Ch,
         __nv_bfloat16* __restrict__ Cl, int N, int K,
         const float* __restrict__ bias, const float* __restrict__ res, int relu) {
    extern __shared__ char smem[];
    const uint32_t sb = smem_u32(smem);
    const int tid = threadIdx.x;
    const int lane = tid & 31;
    const int w = tid >> 5;
    const int wm = (w & 1) * 64;
    const int wn = (w >> 1) * 32;
    const int m0 = blockIdx.x * GBM;
    const int n0 = blockIdx.y * GBN;
    const int NK = K >> 5;

    float acc[4][4][4];
    #pragma unroll
    for (int i = 0; i < 4; i++)
        #pragma unroll
        for (int j = 0; j < 4; j++)
            #pragma unroll
            for (int e = 0; e < 4; e++) acc[i][j][e] = 0.f;

#define ISSUE(IT) do {                                                        \
        int kt = (IT) << 5;                                                   \
        int bufo = ((IT) & 1) * STG;                                          \
        char* st = smem + bufo;                                               \
        uint32_t stu = sb + bufo;                                             \
        _Pragma("unroll")                                                     \
        for (int i = 0; i < 2; i++) {                                         \
            int idx = tid + (i << 8);                                         \
            int row = idx >> 2, cq = idx & 3;                                 \
            uint32_t off = sw_off(row, cq);                                   \
            size_t ga = (size_t)(m0 + row) * K + kt + (cq << 3);              \
            cpa(stu + off, Ah + ga);                                          \
            cpa(stu + 8192 + off, Al + ga);                                   \
            int n = n0 + row;                                                 \
            if (n < N) {                                                      \
                size_t gb = (size_t)n * K + kt + (cq << 3);                   \
                cpa(stu + 16384 + off, Bh + gb);                              \
                cpa(stu + 24576 + off, Bl + gb);                              \
            } else {                                                          \
                uint4 z = make_uint4(0, 0, 0, 0);                             \
                *(uint4*)(st + 16384 + off) = z;                              \
                *(uint4*)(st + 24576 + off) = z;                              \
            }                                                                 \
        }                                                                     \
        asm volatile("cp.async.commit_group;" ::: "memory");                  \
    } while (0)

    const int r8  = lane & 7;
    const int oct = lane >> 3;

    ISSUE(0);
    for (int it = 0; it < NK; it++) {
        const bool hn = (it + 1) < NK;
        if (hn) ISSUE(it + 1);
        if (hn) asm volatile("cp.async.wait_group 1;" ::: "memory");
        else    asm volatile("cp.async.wait_group 0;" ::: "memory");
        __syncthreads();

        const uint32_t base = sb + (it & 1) * STG;
        #pragma unroll
        for (int ks = 0; ks < 2; ks++) {
            uint32_t bH[4][2], bL[4][2], aF[4][4];
            #pragma unroll
            for (int p = 0; p < 2; p++) {
                int n = wn + p * 16 + (oct >> 1) * 8 + r8;
                int kc = ks * 2 + (oct & 1);
                uint32_t ad = base + 16384 + sw_off(n, kc);
                uint32_t t[4];
                ldsm4(t, ad);
                bH[p * 2][0] = t[0]; bH[p * 2][1] = t[1];
                bH[p * 2 + 1][0] = t[2]; bH[p * 2 + 1][1] = t[3];
                ldsm4(t, ad + 8192);
                bL[p * 2][0] = t[0]; bL[p * 2][1] = t[1];
                bL[p * 2 + 1][0] = t[2]; bL[p * 2 + 1][1] = t[3];
            }
            #pragma unroll
            for (int mt = 0; mt < 4; mt++) {
                int row = wm + mt * 16 + (oct & 1) * 8 + r8;
                int kc = ks * 2 + (oct >> 1);
                ldsm4(aF[mt], base + sw_off(row, kc));
            }
            #pragma unroll
            for (int mt = 0; mt < 4; mt++)
                #pragma unroll
                for (int nt = 0; nt < 4; nt++) {
                    mma_bf16(acc[mt][nt], aF[mt], bH[nt]);
                    mma_bf16(acc[mt][nt], aF[mt], bL[nt]);
                }
            #pragma unroll
            for (int mt = 0; mt < 4; mt++) {
                int row = wm + mt * 16 + (oct & 1) * 8 + r8;
                int kc = ks * 2 + (oct >> 1);
                ldsm4(aF[mt], base + 8192 + sw_off(row, kc));
            }
            #pragma unroll
            for (int mt = 0; mt < 4; mt++)
                #pragma unroll
                for (int nt = 0; nt < 4; nt++)
                    mma_bf16(acc[mt][nt], aF[mt], bH[nt]);
        }
        __syncthreads();
    }
#undef ISSUE

    // -------- epilogue --------
    const int g2 = lane >> 2;
    const int t2 = (lane & 3) * 2;

    if (C) {
        const bool fast = (n0 + GBN <= N) && ((N & 1) == 0);
        #pragma unroll
        for (int mt = 0; mt < 4; mt++) {
            #pragma unroll
            for (int nt = 0; nt < 4; nt++) {
                float* c = acc[mt][nt];
                int row = m0 + wm + mt * 16 + g2;
                int col = n0 + wn + nt * 8 + t2;
                if (fast) {
                    float2 v0 = make_float2(c[0], c[1]);
                    float2 v1 = make_float2(c[2], c[3]);
                    if (bias) {
                        float2 bb = *(const float2*)(bias + col);
                        v0.x += bb.x; v0.y += bb.y; v1.x += bb.x; v1.y += bb.y;
                    }
                    if (res) {
                        float2 r0 = *(const float2*)(res + (size_t)row * N + col);
                        float2 r1 = *(const float2*)(res + (size_t)(row + 8) * N + col);
                        v0.x += r0.x; v0.y += r0.y; v1.x += r1.x; v1.y += r1.y;
                    }
                    if (relu) {
                        v0.x = fmaxf(v0.x, 0.f); v0.y = fmaxf(v0.y, 0.f);
                        v1.x = fmaxf(v1.x, 0.f); v1.y = fmaxf(v1.y, 0.f);
                    }
                    *(float2*)(C + (size_t)row * N + col) = v0;
                    *(float2*)(C + (size_t)(row + 8) * N + col) = v1;
                } else {
                    #pragma unroll
                    for (int e = 0; e < 2; e++) {
                        int nn = col + e;
                        if (nn < N) {
                            float v0 = c[e], v1 = c[2 + e];
                            if (bias) { float bb = bias[nn]; v0 += bb; v1 += bb; }
                            if (res) {
                                v0 += res[(size_t)row * N + nn];
                                v1 += res[(size_t)(row + 8) * N + nn];
                            }
                            if (relu) { v0 = fmaxf(v0, 0.f); v1 = fmaxf(v1, 0.f); }
                            C[(size_t)row * N + nn] = v0;
                            C[(size_t)(row + 8) * N + nn] = v1;
                        }
                    }
                }
            }
        }
    } else {
        // split bf16 output (N even, full tiles)
        #pragma unroll
        for (int mt = 0; mt < 4; mt++) {
            #pragma unroll
            for (int nt = 0; nt < 4; nt++) {
                float* c = acc[mt][nt];
                int row = m0 + wm + mt * 16 + g2;
                int col = n0 + wn + nt * 8 + t2;
                float v[4] = {c[0], c[1], c[2], c[3]};
                if (bias) {
                    float2 bb = *(const float2*)(bias + col);
                    v[0] += bb.x; v[1] += bb.y; v[2] += bb.x; v[3] += bb.y;
                }
                if (relu) {
                    v[0] = fmaxf(v[0], 0.f); v[1] = fmaxf(v[1], 0.f);
                    v[2] = fmaxf(v[2], 0.f); v[3] = fmaxf(v[3], 0.f);
                }
                __nv_bfloat16 h0, l0, h1, l1;
                split1(v[0], h0, l0); split1(v[1], h1, l1);
                *(__nv_bfloat162*)(Ch + (size_t)row * N + col) = __halves2bfloat162(h0, h1);
                *(__nv_bfloat162*)(Cl + (size_t)row * N + col) = __halves2bfloat162(l0, l1);
                split1(v[2], h0, l0); split1(v[3], h1, l1);
                *(__nv_bfloat162*)(Ch + (size_t)(row + 8) * N + col) = __halves2bfloat162(h0, h1);
                *(__nv_bfloat162*)(Cl + (size_t)(row + 8) * N + col) = __halves2bfloat162(l0, l1);
            }
        }
    }
}

// ---------------- attention (fp32 SIMT over fused qkv buffer) ----------------
#define BM 128
#define BN 64
#define BK 16

__global__ void __launch_bounds__(256)
attn_scores(const float* __restrict__ qkv) {
    int z = blockIdx.z;
    int b = z / NH, h = z % NH;
    const float* A  = qkv + (size_t)b * TSEQ * QKVW + DM + h * HDIM;     // k
    const float* Bq = qkv + (size_t)b * TSEQ * QKVW + h * HDIM;          // q
    float* Cs = g_scores + (size_t)z * TSEQ * TSEQ;

    __shared__ float As[BK][BM];
    __shared__ float Bs[BK][BN];
    int tid = threadIdx.x;
    int tx = tid & 15, ty = tid >> 4;
    int m0 = blockIdx.y * BM, n0 = blockIdx.x * BN;
    float acc[8][4] = {};

    for (int kt = 0; kt < HDIM; kt += BK) {
        #pragma unroll
        for (int i = 0; i < 2; i++) {
            int v = tid + i * 256;
            int r = v >> 2, c4 = (v & 3) * 4;
            float4 a = *(const float4*)(A + (size_t)(m0 + r) * QKVW + kt + c4);
            As[c4 + 0][r] = a.x; As[c4 + 1][r] = a.y;
            As[c4 + 2][r] = a.z; As[c4 + 3][r] = a.w;
        }
        {
            int n = tid >> 2, c4 = (tid & 3) * 4;
            float4 q4 = *(const float4*)(Bq + (size_t)(n0 + n) * QKVW + kt + c4);
            Bs[c4 + 0][n] = q4.x; Bs[c4 + 1][n] = q4.y;
            Bs[c4 + 2][n] = q4.z; Bs[c4 + 3][n] = q4.w;
        }
        __syncthreads();
        #pragma unroll
        for (int k = 0; k < BK; k++) {
            float4 a0 = *(const float4*)&As[k][ty * 8];
            float4 a1 = *(const float4*)&As[k][ty * 8 + 4];
            float4 b0 = *(const float4*)&Bs[k][tx * 4];
            float am[8] = {a0.x, a0.y, a0.z, a0.w, a1.x, a1.y, a1.z, a1.w};
            float bn[4] = {b0.x, b0.y, b0.z, b0.w};
            #pragma unroll
            for (int i = 0; i < 8; i++)
                #pragma unroll
                for (int j = 0; j < 4; j++)
                    acc[i][j] += am[i] * bn[j];
        }
        __syncthreads();
    }

    const float NEG_INF = __int_as_float(0xff800000);
    #pragma unroll
    for (int i = 0; i < 8; i++) {
        int t = m0 + ty * 8 + i;
        #pragma unroll
        for (int j = 0; j < 4; j++) {
            int s = n0 + tx * 4 + j;
            Cs[(size_t)t * TSEQ + s] = (s <= t) ? acc[i][j] : NEG_INF;
        }
    }
}

__global__ void softmax_kernel() {
    size_t row = blockIdx.x;
    float* w = g_scores + row * TSEQ;
    int tid = threadIdx.x;
    float v0 = w[tid], v1 = w[tid + 256];
    __shared__ float sh[256];
    sh[tid] = fmaxf(v0, v1);
    __syncthreads();
    for (int o = 128; o; o >>= 1) {
        if (tid < o) sh[tid] = fmaxf(sh[tid], sh[tid + o]);
        __syncthreads();
    }
    float m = sh[0];
    __syncthreads();
    float e0 = expf(v0 - m), e1 = expf(v1 - m);
    sh[tid] = e0 + e1;
    __syncthreads();
    for (int o = 128; o; o >>= 1) {
        if (tid < o) sh[tid] += sh[tid + o];
        __syncthreads();
    }
    float inv = 1.f / sh[0];
    w[tid] = e0 * inv;
    w[tid + 256] = e1 * inv;
}

__global__ void __launch_bounds__(256)
attn_av(const float* __restrict__ qkv) {
    int z = blockIdx.z;
    int b = z / NH, h = z % NH;
    const float* A  = g_scores + (size_t)z * TSEQ * TSEQ;
    const float* Bv = qkv + (size_t)b * TSEQ * QKVW + 2 * DM + h * HDIM;

    __shared__ float As[BK][BM];
    __shared__ float Bs[BK][BN];
    int tid = threadIdx.x;
    int tx = tid & 15, ty = tid >> 4;
    int m0 = blockIdx.y * BM;
    float acc[8][4] = {};

    for (int kt = 0; kt < TSEQ; kt += BK) {
        #pragma unroll
        for (int i = 0; i < 2; i++) {
            int v = tid + i * 256;
            int r = v >> 2, c4 = (v & 3) * 4;
            float4 a = *(const float4*)(A + (size_t)(m0 + r) * TSEQ + kt + c4);
            As[c4 + 0][r] = a.x; As[c4 + 1][r] = a.y;
            As[c4 + 2][r] = a.z; As[c4 + 3][r] = a.w;
        }
        #pragma unroll
        for (int j = 0; j < 4; j++) {
            int k = (tid >> 6) + j * 4;
            int n = tid & 63;
            Bs[k][n] = Bv[(size_t)(kt + k) * QKVW + n];
        }
        __syncthreads();
        #pragma unroll
        for (int k = 0; k < BK; k++) {
            float4 a0 = *(const float4*)&As[k][ty * 8];
            float4 a1 = *(const float4*)&As[k][ty * 8 + 4];
            float4 b0 = *(const float4*)&Bs[k][tx * 4];
            float am[8] = {a0.x, a0.y, a0.z, a0.w, a1.x, a1.y, a1.z, a1.w};
            float bn[4] = {b0.x, b0.y, b0.z, b0.w};
            #pragma unroll
            for (int i = 0; i < 8; i++)
                #pragma unroll
                for (int j = 0; j < 4; j++)
                    acc[i][j] += am[i] * bn[j];
        }
        __syncthreads();
    }

    #pragma unroll
    for (int i = 0; i < 8; i++) {
        int t = m0 + ty * 8 + i;
        size_t o = ((size_t)b * TSEQ + t) * DM + h * HDIM + tx * 4;
        #pragma unroll
        for (int j = 0; j < 4; j++) {
            __nv_bfloat16 hh, ll;
            split1(acc[i][j], hh, ll);
            g_ath[o + j] = hh;
            g_atl[o + j] = ll;
        }
    }
}

// ---------------- loss ----------------
__global__ void loss_kernel(const float* __restrict__ logits,
                            const int* __restrict__ target) {
    int row = blockIdx.x;
    const float* lg = logits + (size_t)row * VCAB;
    int tid = threadIdx.x;
    float m = -FLT_MAX, s = 0.f;
    for (int i = tid; i < VCAB; i += blockDim.x) {
        float v = lg[i];
        if (v > m) { s = s * expf(m - v) + 1.f; m = v; }
        else       { s += expf(v - m); }
    }
    __shared__ float sm[256], ss[256];
    sm[tid] = m; ss[tid] = s;
    __syncthreads();
    for (int o = 128; o; o >>= 1) {
        if (tid < o) {
            float m2 = sm[tid + o], s2 = ss[tid + o];
            float mm = fmaxf(sm[tid], m2);
            ss[tid] = ss[tid] * expf(sm[tid] - mm) + s2 * expf(m2 - mm);
            sm[tid] = mm;
        }
        __syncthreads();
    }
    if (tid == 0) {
        float lse = sm[0] + logf(ss[0]);
        g_nll[row] = lse - lg[target[row]];
    }
}

__global__ void loss_reduce(float* out) {
    __shared__ float sh[256];
    float s = 0.f;
    for (int i = threadIdx.x; i < NTOK; i += 256) s += g_nll[i];
    sh[threadIdx.x] = s;
    __syncthreads();
    for (int o = 128; o; o >>= 1) {
        if (threadIdx.x < o) sh[threadIdx.x] += sh[threadIdx.x + o];
        __syncthreads();
    }
    if (threadIdx.x == 0) out[0] = sh[0] * (1.f / NTOK);
}

// ---------------- host ----------------
extern "C" void kernel_launch(void* const* d_in, const int* in_sizes, int n_in,
                              void* d_out, int out_size) {
    const int*   x_ids      = (const int*)d_in[0];
    const int*   target     = (const int*)d_in[1];
    const float* tok_emb    = (const float*)d_in[2];
    const float* pos_emb    = (const float*)d_in[3];
    const float* in_proj_w  = (const float*)d_in[4];
    const float* in_proj_b  = (const float*)d_in[5];
    const float* wk         = (const float*)d_in[6];
    const float* bk         = (const float*)d_in[7];
    const float* wq         = (const float*)d_in[8];
    const float* bq         = (const float*)d_in[9];
    const float* wv         = (const float*)d_in[10];
    const float* bv         = (const float*)d_in[11];
    const float* out_proj_w = (const float*)d_in[12];
    const float* out_proj_b = (const float*)d_in[13];
    const float* ff_w1      = (const float*)d_in[14];
    const float* ff_b1      = (const float*)d_in[15];
    const float* ff_w2      = (const float*)d_in[16];
    const float* ff_b2      = (const float*)d_in[17];
    const float* lna_g      = (const float*)d_in[18];
    const float* lna_b      = (const float*)d_in[19];
    const float* lnf_g      = (const float*)d_in[20];
    const float* lnf_b      = (const float*)d_in[21];
    const float* out_w      = (const float*)d_in[22];
    const float* out_b      = (const float*)d_in[23];

    float *px, *pqkv, *plog, *pbqkv;
    cudaGetSymbolAddress((void**)&px,    g_x);
    cudaGetSymbolAddress((void**)&pqkv,  g_qkv);
    cudaGetSymbolAddress((void**)&plog,  g_logits_scratch);
    cudaGetSymbolAddress((void**)&pbqkv, g_bqkv);

    __nv_bfloat16 *ah, *al, *h2h, *h2l, *ath, *atl, *ffh, *ffl;
    cudaGetSymbolAddress((void**)&ah,  g_ah);  cudaGetSymbolAddress((void**)&al,  g_al);
    cudaGetSymbolAddress((void**)&h2h, g_h2h); cudaGetSymbolAddress((void**)&h2l, g_h2l);
    cudaGetSymbolAddress((void**)&ath, g_ath); cudaGetSymbolAddress((void**)&atl, g_atl);
    cudaGetSymbolAddress((void**)&ffh, g_ffh); cudaGetSymbolAddress((void**)&ffl, g_ffl);

    __nv_bfloat16 *tqkv_h, *tqkv_l, *tin_h, *tin_l, *top_h, *top_l;
    __nv_bfloat16 *tf1_h, *tf1_l, *tf2_h, *tf2_l, *tow_h, *tow_l;
    cudaGetSymbolAddress((void**)&tqkv_h, g_tqkv_h); cudaGetSymbolAddress((void**)&tqkv_l, g_tqkv_l);
    cudaGetSymbolAddress((void**)&tin_h, g_tin_h); cudaGetSymbolAddress((void**)&tin_l, g_tin_l);
    cudaGetSymbolAddress((void**)&top_h, g_top_h); cudaGetSymbolAddress((void**)&top_l, g_top_l);
    cudaGetSymbolAddress((void**)&tf1_h, g_tf1_h); cudaGetSymbolAddress((void**)&tf1_l, g_tf1_l);
    cudaGetSymbolAddress((void**)&tf2_h, g_tf2_h); cudaGetSymbolAddress((void**)&tf2_l, g_tf2_l);
    cudaGetSymbolAddress((void**)&tow_h, g_tow_h); cudaGetSymbolAddress((void**)&tow_l, g_tow_l);

    cudaFuncSetAttribute(gemm_mma, cudaFuncAttributeMaxDynamicSharedMemorySize, SM_DYN);

    const size_t LOGITS_N = (size_t)NTOK * VCAB;
    float* logits = ((size_t)out_size >= LOGITS_N) ? (float*)d_out : plog;

    embed_kernel<<<(NTOK * DM + 255) / 256, 256>>>(x_ids, tok_emb, pos_emb);

    dim3 tb(32, 8);
    repack_qkv_t<<<dim3(2, 24, NL * NH), tb>>>(wq, wk, wv);
    repack_t<<<dim3(24, 24, NL), tb>>>(in_proj_w,  tin_h, tin_l, DM, DM);
    repack_t<<<dim3(24, 24, NL), tb>>>(out_proj_w, top_h, top_l, DM, DM);
    repack_t<<<dim3(96, 24, NL), tb>>>(ff_w1, tf1_h, tf1_l, DM, DFF);
    repack_t<<<dim3(24, 96, NL), tb>>>(ff_w2, tf2_h, tf2_l, DFF, DM);
    repack_t<<<dim3((VCAB + 31) / 32, 24, 1), tb>>>(out_w, tow_h, tow_l, DM, VCAB);
    bias_concat<<<(NL * QKVW + 255) / 256, 256>>>(bq, bk, bv);

    dim3 blk(256);
    dim3 g_dm(NTOK / GBM, DM / GBN);                  // (16, 6)
    dim3 g_qkvg(NTOK / GBM, QKVW / GBN);              // (16, 18)
    dim3 g_ff1(NTOK / GBM, DFF / GBN);                // (16, 24)
    dim3 g_lm(NTOK / GBM, (VCAB + GBN - 1) / GBN);    // (16, 393)
    dim3 g_sc(TSEQ / BN, TSEQ / BM, BBAT * NH);
    dim3 g_av(1, TSEQ / BM, BBAT * NH);

    for (int l = 0; l < NL; l++) {
        size_t wd = (size_t)l * DM * DM;
        size_t wqk = (size_t)l * QKVW * DM;
        size_t wf = (size_t)l * DM * DFF;
        ln_kernel<<<NTOK, 256>>>(px, ah, al, lna_g + l * DM, lna_b + l * DM);
        gemm_mma<<<g_dm, blk, SM_DYN>>>(ah, al, tin_h + wd, tin_l + wd,
                                        nullptr, h2h, h2l, DM, DM,
                                        in_proj_b + l * DM, nullptr, 0);
        gemm_mma<<<g_qkvg, blk, SM_DYN>>>(h2h, h2l, tqkv_h + wqk, tqkv_l + wqk,
                                          pqkv, nullptr, nullptr, QKVW, DM,
                                          pbqkv + l * QKVW, nullptr, 0);
        attn_scores<<<g_sc, blk>>>(pqkv);
        softmax_kernel<<<BBAT * NH * TSEQ, 256>>>();
        attn_av<<<g_av, blk>>>(pqkv);
        gemm_mma<<<g_dm, blk, SM_DYN>>>(ath, atl, top_h + wd, top_l + wd,
                                        px, nullptr, nullptr, DM, DM,
                                        out_proj_b + l * DM, px, 0);
        ln_kernel<<<NTOK, 256>>>(px, ah, al, lnf_g + l * DM, lnf_b + l * DM);
        gemm_mma<<<g_ff1, blk, SM_DYN>>>(ah, al, tf1_h + wf, tf1_l + wf,
                                         nullptr, ffh, ffl, DFF, DM,
                                         ff_b1 + l * DFF, nullptr, 1);
        gemm_mma<<<g_dm, blk, SM_DYN>>>(ffh, ffl, tf2_h + wf, tf2_l + wf,
                                        px, nullptr, nullptr, DM, DFF,
                                        ff_b2 + l * DM, px, 0);
    }

    split_act<<<(NTOK * DM + 255) / 256, 256>>>(px, ah, al, NTOK * DM);
    gemm_mma<<<g_lm, blk, SM_DYN>>>(ah, al, tow_h, tow_l,
                                    logits, nullptr, nullptr, VCAB, DM,
                                    out_b, nullptr, 0);

    if ((size_t)out_size != LOGITS_N) {
        loss_kernel<<<NTOK, 256>>>(logits, target);
        loss_reduce<<<1, 256>>>((float*)d_out + (out_size - 1));
    }
}

// round 5
// speedup vs baseline: 2.7856x; 1.0702x over previous
#include <cuda_runtime.h>
#include <cuda_bf16.h>
#include <math.h>
#include <float.h>
#include <stdint.h>

// ---------------- model constants ----------------
#define VCAB 50257
#define DM   768
#define NL   6
#define NH   12
#define HDIM 64
#define BBAT 4
#define TSEQ 512
#define NTOK (BBAT * TSEQ)     // 2048
#define DFF  (4 * DM)          // 3072
#define QKVW (3 * DM)          // 2304
#define NZ   (BBAT * NH)       // 48

// ---------------- scratch ----------------
__device__ float g_x[NTOK * DM];                       // residual stream (fp32)
__device__ float g_scores[(size_t)NZ * TSEQ * TSEQ];   // attention scores (fp32)
__device__ float g_nll[NTOK];
__device__ float g_logits_scratch[(size_t)NTOK * VCAB];

// split bf16 activations (hi/lo)
__device__ __nv_bfloat16 g_ah[NTOK * DM],  g_al[NTOK * DM];    // LN out / LM-head in
__device__ __nv_bfloat16 g_h2h[NTOK * DM], g_h2l[NTOK * DM];   // in_proj out
__device__ __nv_bfloat16 g_ath[NTOK * DM], g_atl[NTOK * DM];   // attn out
__device__ __nv_bfloat16 g_ffh[NTOK * DFF], g_ffl[NTOK * DFF]; // ff1 out

// per-head split attention operands
__device__ __nv_bfloat16 g_qh[NZ * TSEQ * HDIM], g_ql[NZ * TSEQ * HDIM];
__device__ __nv_bfloat16 g_kh[NZ * TSEQ * HDIM], g_kl[NZ * TSEQ * HDIM];
__device__ __nv_bfloat16 g_vth[NZ * HDIM * TSEQ], g_vtl[NZ * HDIM * TSEQ]; // V^T
__device__ __nv_bfloat16 g_ph[(size_t)NZ * TSEQ * TSEQ], g_pl[(size_t)NZ * TSEQ * TSEQ];

// split bf16 transposed weights [N,K]
__device__ __nv_bfloat16 g_tqkv_h[(size_t)NL * QKVW * DM], g_tqkv_l[(size_t)NL * QKVW * DM];
__device__ __nv_bfloat16 g_tin_h[NL * DM * DM], g_tin_l[NL * DM * DM];
__device__ __nv_bfloat16 g_top_h[NL * DM * DM], g_top_l[NL * DM * DM];
__device__ __nv_bfloat16 g_tf1_h[NL * DM * DFF], g_tf1_l[NL * DM * DFF];
__device__ __nv_bfloat16 g_tf2_h[NL * DM * DFF], g_tf2_l[NL * DM * DFF];
__device__ __nv_bfloat16 g_tow_h[(size_t)VCAB * DM], g_tow_l[(size_t)VCAB * DM];
__device__ float g_bqkv[NL * QKVW];

// ---------------- helpers ----------------
static __device__ __forceinline__ uint32_t smem_u32(const void* p) {
    uint32_t a;
    asm("{ .reg .u64 t; cvta.to.shared.u64 t, %1; cvt.u32.u64 %0, t; }"
        : "=r"(a) : "l"(p));
    return a;
}
static __device__ __forceinline__ void ldsm4(uint32_t* r, uint32_t addr) {
    asm volatile("ldmatrix.sync.aligned.m8n8.x4.shared.b16 {%0,%1,%2,%3}, [%4];"
                 : "=r"(r[0]), "=r"(r[1]), "=r"(r[2]), "=r"(r[3]) : "r"(addr));
}
static __device__ __forceinline__ void mma_bf16(float* c, const uint32_t* a,
                                                const uint32_t* b) {
    asm volatile(
        "mma.sync.aligned.m16n8k16.row.col.f32.bf16.bf16.f32 "
        "{%0,%1,%2,%3}, {%4,%5,%6,%7}, {%8,%9}, {%0,%1,%2,%3};"
        : "+f"(c[0]), "+f"(c[1]), "+f"(c[2]), "+f"(c[3])
        : "r"(a[0]), "r"(a[1]), "r"(a[2]), "r"(a[3]), "r"(b[0]), "r"(b[1]));
}
static __device__ __forceinline__ void cpa(uint32_t dst, const void* src) {
    asm volatile("cp.async.cg.shared.global [%0], [%1], 16;" :: "r"(dst), "l"(src));
}
// swizzled byte offset within an 8KB [128 rows x 32 bf16] region
static __device__ __forceinline__ uint32_t sw_off(int row, int kchunk) {
    return (uint32_t)(row * 64 + ((kchunk ^ ((row >> 1) & 3)) << 4));
}
static __device__ __forceinline__ void split1(float v, __nv_bfloat16& h,
                                              __nv_bfloat16& l) {
    h = __float2bfloat16(v);
    l = __float2bfloat16(v - __bfloat162float(h));
}

// ---------------- shared HMMA mainloop ----------------
// acc[mt][nt][e] += Ah*Bh + Ah*Bl + Al*Bh over NK k-iters (BK=32).
// A [M,Kst] split bf16, rows m0..m0+127 valid; B [N,Kst] rows >= N zero-filled.
#define GBM 128
#define GBN 128
#define STG 32768
#define SM_DYN (2 * STG)

static __device__ __forceinline__ void mma_loop(
    const __nv_bfloat16* __restrict__ Ah, const __nv_bfloat16* __restrict__ Al,
    const __nv_bfloat16* __restrict__ Bh, const __nv_bfloat16* __restrict__ Bl,
    int m0, int n0, int N, int Kst, int NK, char* smem, float acc[4][4][4]) {
    const uint32_t sb = smem_u32(smem);
    const int tid = threadIdx.x;
    const int lane = tid & 31;
    const int w = tid >> 5;
    const int wm = (w & 1) * 64;
    const int wn = (w >> 1) * 32;
    const int r8  = lane & 7;
    const int oct = lane >> 3;

#define ISSUE(IT) do {                                                        \
        int kt = (IT) << 5;                                                   \
        int bufo = ((IT) & 1) * STG;                                          \
        char* st = smem + bufo;                                               \
        uint32_t stu = sb + bufo;                                             \
        _Pragma("unroll")                                                     \
        for (int i = 0; i < 2; i++) {                                         \
            int idx = tid + (i << 8);                                         \
            int row = idx >> 2, cq = idx & 3;                                 \
            uint32_t off = sw_off(row, cq);                                   \
            size_t ga = (size_t)(m0 + row) * Kst + kt + (cq << 3);            \
            cpa(stu + off, Ah + ga);                                          \
            cpa(stu + 8192 + off, Al + ga);                                   \
            int n = n0 + row;                                                 \
            if (n < N) {                                                      \
                size_t gb = (size_t)n * Kst + kt + (cq << 3);                 \
                cpa(stu + 16384 + off, Bh + gb);                              \
                cpa(stu + 24576 + off, Bl + gb);                              \
            } else {                                                          \
                uint4 z4 = make_uint4(0, 0, 0, 0);                            \
                *(uint4*)(st + 16384 + off) = z4;                             \
                *(uint4*)(st + 24576 + off) = z4;                             \
            }                                                                 \
        }                                                                     \
        asm volatile("cp.async.commit_group;" ::: "memory");                  \
    } while (0)

    ISSUE(0);
    for (int it = 0; it < NK; it++) {
        const bool hn = (it + 1) < NK;
        if (hn) ISSUE(it + 1);
        if (hn) asm volatile("cp.async.wait_group 1;" ::: "memory");
        else    asm volatile("cp.async.wait_group 0;" ::: "memory");
        __syncthreads();

        const uint32_t base = sb + (it & 1) * STG;
        #pragma unroll
        for (int ks = 0; ks < 2; ks++) {
            uint32_t bH[4][2], bL[4][2], aF[4][4];
            #pragma unroll
            for (int p = 0; p < 2; p++) {
                int n = wn + p * 16 + (oct >> 1) * 8 + r8;
                int kc = ks * 2 + (oct & 1);
                uint32_t ad = base + 16384 + sw_off(n, kc);
                uint32_t t[4];
                ldsm4(t, ad);
                bH[p * 2][0] = t[0]; bH[p * 2][1] = t[1];
                bH[p * 2 + 1][0] = t[2]; bH[p * 2 + 1][1] = t[3];
                ldsm4(t, ad + 8192);
                bL[p * 2][0] = t[0]; bL[p * 2][1] = t[1];
                bL[p * 2 + 1][0] = t[2]; bL[p * 2 + 1][1] = t[3];
            }
            #pragma unroll
            for (int mt = 0; mt < 4; mt++) {
                int row = wm + mt * 16 + (oct & 1) * 8 + r8;
                int kc = ks * 2 + (oct >> 1);
                ldsm4(aF[mt], base + sw_off(row, kc));
            }
            #pragma unroll
            for (int mt = 0; mt < 4; mt++)
                #pragma unroll
                for (int nt = 0; nt < 4; nt++) {
                    mma_bf16(acc[mt][nt], aF[mt], bH[nt]);
                    mma_bf16(acc[mt][nt], aF[mt], bL[nt]);
                }
            #pragma unroll
            for (int mt = 0; mt < 4; mt++) {
                int row = wm + mt * 16 + (oct & 1) * 8 + r8;
                int kc = ks * 2 + (oct >> 1);
                ldsm4(aF[mt], base + 8192 + sw_off(row, kc));
            }
            #pragma unroll
            for (int mt = 0; mt < 4; mt++)
                #pragma unroll
                for (int nt = 0; nt < 4; nt++)
                    mma_bf16(acc[mt][nt], aF[mt], bH[nt]);
        }
        __syncthreads();
    }
#undef ISSUE
}

// ---------------- embedding ----------------
__global__ void embed_kernel(const int* __restrict__ ids,
                             const float* __restrict__ tok,
                             const float* __restrict__ pos) {
    int i = blockIdx.x * blockDim.x + threadIdx.x;
    if (i >= NTOK * DM) return;
    int row = i / DM, d = i - row * DM;
    int t = row % TSEQ;
    g_x[i] = tok[(size_t)ids[row] * DM + d] + pos[t * DM + d];
}

// ---------------- weight repack: [K,N] fp32 -> [N,K] bf16 hi/lo ----------------
__global__ void repack_t(const float* __restrict__ src,
                         __nv_bfloat16* __restrict__ dh,
                         __nv_bfloat16* __restrict__ dl, int K, int N) {
    __shared__ float t[32][33];
    size_t mo = (size_t)blockIdx.z * K * N;
    int k0 = blockIdx.y * 32, n0 = blockIdx.x * 32;
    int tx = threadIdx.x, ty = threadIdx.y;
    for (int i = ty; i < 32; i += 8) {
        int k = k0 + i, n = n0 + tx;
        t[i][tx] = (k < K && n < N) ? src[mo + (size_t)k * N + n] : 0.f;
    }
    __syncthreads();
    for (int i = ty; i < 32; i += 8) {
        int n = n0 + i, k = k0 + tx;
        if (n < N && k < K) {
            __nv_bfloat16 h, l;
            split1(t[tx][i], h, l);
            size_t o = mo + (size_t)n * K + k;
            dh[o] = h; dl[o] = l;
        }
    }
}

// qkv: [L,H,D,HD] -> per layer combined [q|k|v][2304, 768] bf16 hi/lo
__global__ void repack_qkv_t(const float* __restrict__ wq,
                             const float* __restrict__ wk,
                             const float* __restrict__ wv) {
    __shared__ float tq[32][33], tk[32][33], tv[32][33];
    int z = blockIdx.z, l = z / NH, h = z % NH;
    int d0 = blockIdx.y * 32, e0 = blockIdx.x * 32;
    int tx = threadIdx.x, ty = threadIdx.y;
    size_t sbo = ((size_t)l * NH + h) * DM * HDIM;
    for (int i = ty; i < 32; i += 8) {
        int d = d0 + i, e = e0 + tx;
        size_t idx = sbo + (size_t)d * HDIM + e;
        tq[i][tx] = wq[idx]; tk[i][tx] = wk[idx]; tv[i][tx] = wv[idx];
    }
    __syncthreads();
    size_t db = (size_t)l * QKVW * DM;
    for (int i = ty; i < 32; i += 8) {
        int e = e0 + i, d = d0 + tx;
        int nq = h * HDIM + e;
        __nv_bfloat16 hh, ll;
        size_t o;
        o = db + (size_t)nq * DM + d;
        split1(tq[tx][i], hh, ll); g_tqkv_h[o] = hh; g_tqkv_l[o] = ll;
        o = db + (size_t)(DM + nq) * DM + d;
        split1(tk[tx][i], hh, ll); g_tqkv_h[o] = hh; g_tqkv_l[o] = ll;
        o = db + (size_t)(2 * DM + nq) * DM + d;
        split1(tv[tx][i], hh, ll); g_tqkv_h[o] = hh; g_tqkv_l[o] = ll;
    }
}

__global__ void bias_concat(const float* __restrict__ bq,
                            const float* __restrict__ bk,
                            const float* __restrict__ bv) {
    int i = blockIdx.x * blockDim.x + threadIdx.x;
    if (i >= NL * QKVW) return;
    int l = i / QKVW, c = i % QKVW;
    float v = (c < DM) ? bq[l * DM + c]
            : (c < 2 * DM) ? bk[l * DM + c - DM]
            : bv[l * DM + c - 2 * DM];
    g_bqkv[i] = v;
}

// ---------------- layernorm: fp32 in -> split bf16 out ----------------
__global__ void ln_kernel(const float* __restrict__ in,
                          __nv_bfloat16* __restrict__ oh,
                          __nv_bfloat16* __restrict__ ol,
                          const float* __restrict__ g, const float* __restrict__ b) {
    int row = blockIdx.x;
    const float* x = in + (size_t)row * DM;
    float s = 0.f, s2 = 0.f;
    for (int i = threadIdx.x; i < DM; i += blockDim.x) {
        float v = x[i];
        s += v; s2 += v * v;
    }
    __shared__ float rs[32], rs2[32];
    for (int o = 16; o; o >>= 1) {
        s  += __shfl_down_sync(0xffffffffu, s, o);
        s2 += __shfl_down_sync(0xffffffffu, s2, o);
    }
    int wid = threadIdx.x >> 5, lid = threadIdx.x & 31;
    if (lid == 0) { rs[wid] = s; rs2[wid] = s2; }
    __syncthreads();
    if (wid == 0) {
        int nw = blockDim.x >> 5;
        s  = (lid < nw) ? rs[lid]  : 0.f;
        s2 = (lid < nw) ? rs2[lid] : 0.f;
        for (int o = 16; o; o >>= 1) {
            s  += __shfl_down_sync(0xffffffffu, s, o);
            s2 += __shfl_down_sync(0xffffffffu, s2, o);
        }
        if (lid == 0) { rs[0] = s; rs2[0] = s2; }
    }
    __syncthreads();
    float mean = rs[0] * (1.f / DM);
    float var  = rs2[0] * (1.f / DM) - mean * mean;
    float inv  = rsqrtf(var + 1e-5f);
    for (int i = threadIdx.x; i < DM; i += blockDim.x) {
        float v = (x[i] - mean) * inv * g[i] + b[i];
        __nv_bfloat16 h, l;
        split1(v, h, l);
        oh[(size_t)row * DM + i] = h;
        ol[(size_t)row * DM + i] = l;
    }
}

// ---------------- split fp32 activation -> bf16 hi/lo ----------------
__global__ void split_act(const float* __restrict__ x,
                          __nv_bfloat16* __restrict__ oh,
                          __nv_bfloat16* __restrict__ ol, int n) {
    int i = blockIdx.x * blockDim.x + threadIdx.x;
    if (i >= n) return;
    __nv_bfloat16 h, l;
    split1(x[i], h, l);
    oh[i] = h; ol[i] = l;
}

// ---------------- weight GEMM kernel ----------------
// mode 0: fp32 C (+bias,+res,+relu); mode 1: split bf16 Ch/Cl (+bias,+relu);
// mode 2: qkv scatter into per-head split buffers (+bias).
__global__ void __launch_bounds__(256, 2)
gemm_mma(const __nv_bfloat16* __restrict__ Ah, const __nv_bfloat16* __restrict__ Al,
         const __nv_bfloat16* __restrict__ Bh, const __nv_bfloat16* __restrict__ Bl,
         float* __restrict__ C, __nv_bfloat16* __restrict__ Ch,
         __nv_bfloat16* __restrict__ Cl, int N, int K,
         const float* __restrict__ bias, const float* __restrict__ res,
         int relu, int mode) {
    extern __shared__ char smem[];
    const int m0 = blockIdx.x * GBM;
    const int n0 = blockIdx.y * GBN;
    float acc[4][4][4] = {};
    mma_loop(Ah, Al, Bh, Bl, m0, n0, N, K, K >> 5, smem, acc);

    const int tid = threadIdx.x;
    const int lane = tid & 31;
    const int w = tid >> 5;
    const int wm = (w & 1) * 64;
    const int wn = (w >> 1) * 32;
    const int g2 = lane >> 2;
    const int t2 = (lane & 3) * 2;

    if (mode == 0) {
        const bool fast = (n0 + GBN <= N) && ((N & 1) == 0);
        #pragma unroll
        for (int mt = 0; mt < 4; mt++) {
            #pragma unroll
            for (int nt = 0; nt < 4; nt++) {
                float* c = acc[mt][nt];
                int row = m0 + wm + mt * 16 + g2;
                int col = n0 + wn + nt * 8 + t2;
                if (fast) {
                    float2 v0 = make_float2(c[0], c[1]);
                    float2 v1 = make_float2(c[2], c[3]);
                    if (bias) {
                        float2 bb = *(const float2*)(bias + col);
                        v0.x += bb.x; v0.y += bb.y; v1.x += bb.x; v1.y += bb.y;
                    }
                    if (res) {
                        float2 r0 = *(const float2*)(res + (size_t)row * N + col);
                        float2 r1 = *(const float2*)(res + (size_t)(row + 8) * N + col);
                        v0.x += r0.x; v0.y += r0.y; v1.x += r1.x; v1.y += r1.y;
                    }
                    if (relu) {
                        v0.x = fmaxf(v0.x, 0.f); v0.y = fmaxf(v0.y, 0.f);
                        v1.x = fmaxf(v1.x, 0.f); v1.y = fmaxf(v1.y, 0.f);
                    }
                    *(float2*)(C + (size_t)row * N + col) = v0;
                    *(float2*)(C + (size_t)(row + 8) * N + col) = v1;
                } else {
                    #pragma unroll
                    for (int e = 0; e < 2; e++) {
                        int nn = col + e;
                        if (nn < N) {
                            float v0 = c[e], v1 = c[2 + e];
                            if (bias) { float bb = bias[nn]; v0 += bb; v1 += bb; }
                            if (res) {
                                v0 += res[(size_t)row * N + nn];
                                v1 += res[(size_t)(row + 8) * N + nn];
                            }
                            if (relu) { v0 = fmaxf(v0, 0.f); v1 = fmaxf(v1, 0.f); }
                            C[(size_t)row * N + nn] = v0;
                            C[(size_t)(row + 8) * N + nn] = v1;
                        }
                    }
                }
            }
        }
    } else if (mode == 1) {
        #pragma unroll
        for (int mt = 0; mt < 4; mt++) {
            #pragma unroll
            for (int nt = 0; nt < 4; nt++) {
                float* c = acc[mt][nt];
                int row = m0 + wm + mt * 16 + g2;
                int col = n0 + wn + nt * 8 + t2;
                float v[4] = {c[0], c[1], c[2], c[3]};
                if (bias) {
                    float2 bb = *(const float2*)(bias + col);
                    v[0] += bb.x; v[1] += bb.y; v[2] += bb.x; v[3] += bb.y;
                }
                if (relu) {
                    v[0] = fmaxf(v[0], 0.f); v[1] = fmaxf(v[1], 0.f);
                    v[2] = fmaxf(v[2], 0.f); v[3] = fmaxf(v[3], 0.f);
                }
                __nv_bfloat16 h0, l0, h1, l1;
                split1(v[0], h0, l0); split1(v[1], h1, l1);
                *(__nv_bfloat162*)(Ch + (size_t)row * N + col) = __halves2bfloat162(h0, h1);
                *(__nv_bfloat162*)(Cl + (size_t)row * N + col) = __halves2bfloat162(l0, l1);
                split1(v[2], h0, l0); split1(v[3], h1, l1);
                *(__nv_bfloat162*)(Ch + (size_t)(row + 8) * N + col) = __halves2bfloat162(h0, h1);
                *(__nv_bfloat162*)(Cl + (size_t)(row + 8) * N + col) = __halves2bfloat162(l0, l1);
            }
        }
    } else {
        // qkv scatter: N == 2304, tile lies entirely within one of q/k/v
        #pragma unroll
        for (int mt = 0; mt < 4; mt++) {
            #pragma unroll
            for (int nt = 0; nt < 4; nt++) {
                float* c = acc[mt][nt];
                int row = m0 + wm + mt * 16 + g2;
                int col = n0 + wn + nt * 8 + t2;
                float2 bb = *(const float2*)(bias + col);
                #pragma unroll
                for (int e = 0; e < 4; e++) {
                    int r = row + (e >> 1) * 8;
                    int cc = col + (e & 1);
                    float v = c[e] + ((e & 1) ? bb.y : bb.x);
                    int b = r >> 9, s = r & 511;
                    int sec = cc / DM, d = cc - sec * DM;
                    int h = d >> 6, ee = d & 63;
                    __nv_bfloat16 hh, ll;
                    split1(v, hh, ll);
                    size_t zo = (size_t)(b * NH + h);
                    if (sec == 0) {
                        size_t o = (zo * TSEQ + s) * HDIM + ee;
                        g_qh[o] = hh; g_ql[o] = ll;
                    } else if (sec == 1) {
                        size_t o = (zo * TSEQ + s) * HDIM + ee;
                        g_kh[o] = hh; g_kl[o] = ll;
                    } else {
                        size_t o = (zo * HDIM + ee) * TSEQ + s;
                        g_vth[o] = hh; g_vtl[o] = ll;
                    }
                }
            }
        }
    }
}

// ---------------- attention scores: HMMA, lower-triangular blocks only ----------------
__global__ void __launch_bounds__(256, 2)
attn_sc() {
    extern __shared__ char smem[];
    const int mi_t[10] = {0, 1, 1, 2, 2, 2, 3, 3, 3, 3};
    const int ni_t[10] = {0, 0, 1, 0, 1, 2, 0, 1, 2, 3};
    int z = blockIdx.z;
    int mi = mi_t[blockIdx.x], ni = ni_t[blockIdx.x];
    const __nv_bfloat16* Ah = g_kh + (size_t)z * TSEQ * HDIM;
    const __nv_bfloat16* Al = g_kl + (size_t)z * TSEQ * HDIM;
    const __nv_bfloat16* Bh = g_qh + (size_t)z * TSEQ * HDIM;
    const __nv_bfloat16* Bl = g_ql + (size_t)z * TSEQ * HDIM;
    float acc[4][4][4] = {};
    mma_loop(Ah, Al, Bh, Bl, mi * 128, ni * 128, TSEQ, HDIM, 2, smem, acc);

    const int tid = threadIdx.x;
    const int lane = tid & 31;
    const int w = tid >> 5;
    const int wm = (w & 1) * 64;
    const int wn = (w >> 1) * 32;
    const int g2 = lane >> 2;
    const int t2 = (lane & 3) * 2;
    float* Cs = g_scores + (size_t)z * TSEQ * TSEQ;
    #pragma unroll
    for (int mt = 0; mt < 4; mt++) {
        #pragma unroll
        for (int nt = 0; nt < 4; nt++) {
            float* c = acc[mt][nt];
            int row = mi * 128 + wm + mt * 16 + g2;
            int col = ni * 128 + wn + nt * 8 + t2;
            *(float2*)(Cs + (size_t)row * TSEQ + col) = make_float2(c[0], c[1]);
            *(float2*)(Cs + (size_t)(row + 8) * TSEQ + col) = make_float2(c[2], c[3]);
        }
    }
}

// ---------------- causal softmax: fp32 scores -> split bf16 P ----------------
__global__ void softmax_kernel() {
    int rowg = blockIdx.x;
    int t = rowg & (TSEQ - 1);
    const float* w = g_scores + (size_t)rowg * TSEQ;
    int tid = threadIdx.x;
    bool val0 = (tid <= t), val1 = (tid + 256 <= t);
    float v0 = val0 ? w[tid] : -FLT_MAX;
    float v1 = val1 ? w[tid + 256] : -FLT_MAX;
    __shared__ float sh[256];
    sh[tid] = fmaxf(v0, v1);
    __syncthreads();
    for (int o = 128; o; o >>= 1) {
        if (tid < o) sh[tid] = fmaxf(sh[tid], sh[tid + o]);
        __syncthreads();
    }
    float m = sh[0];
    __syncthreads();
    float e0 = val0 ? expf(v0 - m) : 0.f;
    float e1 = val1 ? expf(v1 - m) : 0.f;
    sh[tid] = e0 + e1;
    __syncthreads();
    for (int o = 128; o; o >>= 1) {
        if (tid < o) sh[tid] += sh[tid + o];
        __syncthreads();
    }
    float inv = 1.f / sh[0];
    size_t ob = (size_t)rowg * TSEQ;
    __nv_bfloat16 h, l;
    split1(e0 * inv, h, l);
    g_ph[ob + tid] = h; g_pl[ob + tid] = l;
    split1(e1 * inv, h, l);
    g_ph[ob + tid + 256] = h; g_pl[ob + tid + 256] = l;
}

// ---------------- attention AV: HMMA, K truncated at diagonal ----------------
__global__ void __launch_bounds__(256, 2)
attn_av() {
    extern __shared__ char smem[];
    int z = blockIdx.z, b = z / NH, h = z % NH;
    int mi = blockIdx.x;
    const __nv_bfloat16* Ah = g_ph + (size_t)z * TSEQ * TSEQ;
    const __nv_bfloat16* Al = g_pl + (size_t)z * TSEQ * TSEQ;
    const __nv_bfloat16* Bh = g_vth + (size_t)z * HDIM * TSEQ;
    const __nv_bfloat16* Bl = g_vtl + (size_t)z * HDIM * TSEQ;
    float acc[4][4][4] = {};
    mma_loop(Ah, Al, Bh, Bl, mi * 128, 0, HDIM, TSEQ, (mi + 1) * 4, smem, acc);

    const int tid = threadIdx.x;
    const int lane = tid & 31;
    const int w = tid >> 5;
    const int wm = (w & 1) * 64;
    const int wn = (w >> 1) * 32;
    const int g2 = lane >> 2;
    const int t2 = (lane & 3) * 2;
    if (wn >= HDIM) return;   // N=64: upper warp columns idle
    #pragma unroll
    for (int mt = 0; mt < 4; mt++) {
        #pragma unroll
        for (int nt = 0; nt < 4; nt++) {
            int col = wn + nt * 8 + t2;
            if (col >= HDIM) continue;
            float* c = acc[mt][nt];
            int t = mi * 128 + wm + mt * 16 + g2;
            size_t o0 = (size_t)(b * TSEQ + t) * DM + h * HDIM + col;
            size_t o1 = (size_t)(b * TSEQ + t + 8) * DM + h * HDIM + col;
            __nv_bfloat16 h0, l0, h1, l1;
            split1(c[0], h0, l0); split1(c[1], h1, l1);
            *(__nv_bfloat162*)(g_ath + o0) = __halves2bfloat162(h0, h1);
            *(__nv_bfloat162*)(g_atl + o0) = __halves2bfloat162(l0, l1);
            split1(c[2], h0, l0); split1(c[3], h1, l1);
            *(__nv_bfloat162*)(g_ath + o1) = __halves2bfloat162(h0, h1);
            *(__nv_bfloat162*)(g_atl + o1) = __halves2bfloat162(l0, l1);
        }
    }
}

// ---------------- loss ----------------
__global__ void loss_kernel(const float* __restrict__ logits,
                            const int* __restrict__ target) {
    int row = blockIdx.x;
    const float* lg = logits + (size_t)row * VCAB;
    int tid = threadIdx.x;
    float m = -FLT_MAX, s = 0.f;
    for (int i = tid; i < VCAB; i += blockDim.x) {
        float v = lg[i];
        if (v > m) { s = s * expf(m - v) + 1.f; m = v; }
        else       { s += expf(v - m); }
    }
    __shared__ float sm[256], ss[256];
    sm[tid] = m; ss[tid] = s;
    __syncthreads();
    for (int o = 128; o; o >>= 1) {
        if (tid < o) {
            float m2 = sm[tid + o], s2 = ss[tid + o];
            float mm = fmaxf(sm[tid], m2);
            ss[tid] = ss[tid] * expf(sm[tid] - mm) + s2 * expf(m2 - mm);
            sm[tid] = mm;
        }
        __syncthreads();
    }
    if (tid == 0) {
        float lse = sm[0] + logf(ss[0]);
        g_nll[row] = lse - lg[target[row]];
    }
}

__global__ void loss_reduce(float* out) {
    __shared__ float sh[256];
    float s = 0.f;
    for (int i = threadIdx.x; i < NTOK; i += 256) s += g_nll[i];
    sh[threadIdx.x] = s;
    __syncthreads();
    for (int o = 128; o; o >>= 1) {
        if (threadIdx.x < o) sh[threadIdx.x] += sh[threadIdx.x + o];
        __syncthreads();
    }
    if (threadIdx.x == 0) out[0] = sh[0] * (1.f / NTOK);
}

// ---------------- host ----------------
extern "C" void kernel_launch(void* const* d_in, const int* in_sizes, int n_in,
                              void* d_out, int out_size) {
    const int*   x_ids      = (const int*)d_in[0];
    const int*   target     = (const int*)d_in[1];
    const float* tok_emb    = (const float*)d_in[2];
    const float* pos_emb    = (const float*)d_in[3];
    const float* in_proj_w  = (const float*)d_in[4];
    const float* in_proj_b  = (const float*)d_in[5];
    const float* wk         = (const float*)d_in[6];
    const float* bk         = (const float*)d_in[7];
    const float* wq         = (const float*)d_in[8];
    const float* bq         = (const float*)d_in[9];
    const float* wv         = (const float*)d_in[10];
    const float* bv         = (const float*)d_in[11];
    const float* out_proj_w = (const float*)d_in[12];
    const float* out_proj_b = (const float*)d_in[13];
    const float* ff_w1      = (const float*)d_in[14];
    const float* ff_b1      = (const float*)d_in[15];
    const float* ff_w2      = (const float*)d_in[16];
    const float* ff_b2      = (const float*)d_in[17];
    const float* lna_g      = (const float*)d_in[18];
    const float* lna_b      = (const float*)d_in[19];
    const float* lnf_g      = (const float*)d_in[20];
    const float* lnf_b      = (const float*)d_in[21];
    const float* out_w      = (const float*)d_in[22];
    const float* out_b      = (const float*)d_in[23];

    float *px, *plog, *pbqkv;
    cudaGetSymbolAddress((void**)&px,    g_x);
    cudaGetSymbolAddress((void**)&plog,  g_logits_scratch);
    cudaGetSymbolAddress((void**)&pbqkv, g_bqkv);

    __nv_bfloat16 *ah, *al, *h2h, *h2l, *ath, *atl, *ffh, *ffl;
    cudaGetSymbolAddress((void**)&ah,  g_ah);  cudaGetSymbolAddress((void**)&al,  g_al);
    cudaGetSymbolAddress((void**)&h2h, g_h2h); cudaGetSymbolAddress((void**)&h2l, g_h2l);
    cudaGetSymbolAddress((void**)&ath, g_ath); cudaGetSymbolAddress((void**)&atl, g_atl);
    cudaGetSymbolAddress((void**)&ffh, g_ffh); cudaGetSymbolAddress((void**)&ffl, g_ffl);

    __nv_bfloat16 *tqkv_h, *tqkv_l, *tin_h, *tin_l, *top_h, *top_l;
    __nv_bfloat16 *tf1_h, *tf1_l, *tf2_h, *tf2_l, *tow_h, *tow_l;
    cudaGetSymbolAddress((void**)&tqkv_h, g_tqkv_h); cudaGetSymbolAddress((void**)&tqkv_l, g_tqkv_l);
    cudaGetSymbolAddress((void**)&tin_h, g_tin_h); cudaGetSymbolAddress((void**)&tin_l, g_tin_l);
    cudaGetSymbolAddress((void**)&top_h, g_top_h); cudaGetSymbolAddress((void**)&top_l, g_top_l);
    cudaGetSymbolAddress((void**)&tf1_h, g_tf1_h); cudaGetSymbolAddress((void**)&tf1_l, g_tf1_l);
    cudaGetSymbolAddress((void**)&tf2_h, g_tf2_h); cudaGetSymbolAddress((void**)&tf2_l, g_tf2_l);
    cudaGetSymbolAddress((void**)&tow_h, g_tow_h); cudaGetSymbolAddress((void**)&tow_l, g_tow_l);

    cudaFuncSetAttribute(gemm_mma, cudaFuncAttributeMaxDynamicSharedMemorySize, SM_DYN);
    cudaFuncSetAttribute(attn_sc,  cudaFuncAttributeMaxDynamicSharedMemorySize, SM_DYN);
    cudaFuncSetAttribute(attn_av,  cudaFuncAttributeMaxDynamicSharedMemorySize, SM_DYN);

    const size_t LOGITS_N = (size_t)NTOK * VCAB;
    float* logits = ((size_t)out_size >= LOGITS_N) ? (float*)d_out : plog;

    embed_kernel<<<(NTOK * DM + 255) / 256, 256>>>(x_ids, tok_emb, pos_emb);

    dim3 tb(32, 8);
    repack_qkv_t<<<dim3(2, 24, NL * NH), tb>>>(wq, wk, wv);
    repack_t<<<dim3(24, 24, NL), tb>>>(in_proj_w,  tin_h, tin_l, DM, DM);
    repack_t<<<dim3(24, 24, NL), tb>>>(out_proj_w, top_h, top_l, DM, DM);
    repack_t<<<dim3(96, 24, NL), tb>>>(ff_w1, tf1_h, tf1_l, DM, DFF);
    repack_t<<<dim3(24, 96, NL), tb>>>(ff_w2, tf2_h, tf2_l, DFF, DM);
    repack_t<<<dim3((VCAB + 31) / 32, 24, 1), tb>>>(out_w, tow_h, tow_l, DM, VCAB);
    bias_concat<<<(NL * QKVW + 255) / 256, 256>>>(bq, bk, bv);

    dim3 blk(256);
    dim3 g_dm(NTOK / GBM, DM / GBN);                  // (16, 6)
    dim3 g_qkvg(NTOK / GBM, QKVW / GBN);              // (16, 18)
    dim3 g_ff1(NTOK / GBM, DFF / GBN);                // (16, 24)
    dim3 g_lm(NTOK / GBM, (VCAB + GBN - 1) / GBN);    // (16, 393)
    dim3 g_sc(10, 1, NZ);
    dim3 g_av(TSEQ / GBM, 1, NZ);

    for (int l = 0; l < NL; l++) {
        size_t wd = (size_t)l * DM * DM;
        size_t wqk = (size_t)l * QKVW * DM;
        size_t wf = (size_t)l * DM * DFF;
        ln_kernel<<<NTOK, 256>>>(px, ah, al, lna_g + l * DM, lna_b + l * DM);
        gemm_mma<<<g_dm, blk, SM_DYN>>>(ah, al, tin_h + wd, tin_l + wd,
                                        nullptr, h2h, h2l, DM, DM,
                                        in_proj_b + l * DM, nullptr, 0, 1);
        gemm_mma<<<g_qkvg, blk, SM_DYN>>>(h2h, h2l, tqkv_h + wqk, tqkv_l + wqk,
                                          nullptr, nullptr, nullptr, QKVW, DM,
                                          pbqkv + l * QKVW, nullptr, 0, 2);
        attn_sc<<<g_sc, blk, SM_DYN>>>();
        softmax_kernel<<<NZ * TSEQ, 256>>>();
        attn_av<<<g_av, blk, SM_DYN>>>();
        gemm_mma<<<g_dm, blk, SM_DYN>>>(ath, atl, top_h + wd, top_l + wd,
                                        px, nullptr, nullptr, DM, DM,
                                        out_proj_b + l * DM, px, 0, 0);
        ln_kernel<<<NTOK, 256>>>(px, ah, al, lnf_g + l * DM, lnf_b + l * DM);
        gemm_mma<<<g_ff1, blk, SM_DYN>>>(ah, al, tf1_h + wf, tf1_l + wf,
                                         nullptr, ffh, ffl, DFF, DM,
                                         ff_b1 + l * DFF, nullptr, 1, 1);
        gemm_mma<<<g_dm, blk, SM_DYN>>>(ffh, ffl, tf2_h + wf, tf2_l + wf,
                                        px, nullptr, nullptr, DM, DFF,
                                        ff_b2 + l * DM, px, 0, 0);
    }

    split_act<<<(NTOK * DM + 255) / 256, 256>>>(px, ah, al, NTOK * DM);
    gemm_mma<<<g_lm, blk, SM_DYN>>>(ah, al, tow_h, tow_l,
                                    logits, nullptr, nullptr, VCAB, DM,
                                    out_b, nullptr, 0, 0);

    if ((size_t)out_size != LOGITS_N) {
        loss_kernel<<<NTOK, 256>>>(logits, target);
        loss_reduce<<<1, 256>>>((float*)d_out + (out_size - 1));
    }
}

// round 7
// speedup vs baseline: 2.8863x; 1.0361x over previous
#include <cuda_runtime.h>
#include <cuda_bf16.h>
#include <math.h>
#include <float.h>
#include <stdint.h>

// ---------------- model constants ----------------
#define VCAB 50257
#define DM   768
#define NL   6
#define NH   12
#define HDIM 64
#define BBAT 4
#define TSEQ 512
#define NTOK (BBAT * TSEQ)     // 2048
#define DFF  (4 * DM)          // 3072
#define QKVW (3 * DM)          // 2304
#define NZ   (BBAT * NH)       // 48

// ---------------- scratch ----------------
__device__ float g_x[NTOK * DM];
__device__ float g_scores[(size_t)NZ * TSEQ * TSEQ];
__device__ float g_nll[NTOK];
__device__ float g_logits_scratch[(size_t)NTOK * VCAB];

__device__ __nv_bfloat16 g_ah[NTOK * DM],  g_al[NTOK * DM];
__device__ __nv_bfloat16 g_h2h[NTOK * DM], g_h2l[NTOK * DM];
__device__ __nv_bfloat16 g_ath[NTOK * DM], g_atl[NTOK * DM];
__device__ __nv_bfloat16 g_ffh[NTOK * DFF], g_ffl[NTOK * DFF];

__device__ __nv_bfloat16 g_qh[NZ * TSEQ * HDIM], g_ql[NZ * TSEQ * HDIM];
__device__ __nv_bfloat16 g_kh[NZ * TSEQ * HDIM], g_kl[NZ * TSEQ * HDIM];
__device__ __nv_bfloat16 g_vth[NZ * HDIM * TSEQ], g_vtl[NZ * HDIM * TSEQ];
__device__ __nv_bfloat16 g_ph[(size_t)NZ * TSEQ * TSEQ], g_pl[(size_t)NZ * TSEQ * TSEQ];

__device__ __nv_bfloat16 g_tqkv_h[(size_t)NL * QKVW * DM], g_tqkv_l[(size_t)NL * QKVW * DM];
__device__ __nv_bfloat16 g_tin_h[NL * DM * DM], g_tin_l[NL * DM * DM];
__device__ __nv_bfloat16 g_top_h[NL * DM * DM], g_top_l[NL * DM * DM];
__device__ __nv_bfloat16 g_tf1_h[NL * DM * DFF], g_tf1_l[NL * DM * DFF];
__device__ __nv_bfloat16 g_tf2_h[NL * DM * DFF], g_tf2_l[NL * DM * DFF];
__device__ __nv_bfloat16 g_tow_h[(size_t)VCAB * DM], g_tow_l[(size_t)VCAB * DM];
__device__ float g_bqkv[NL * QKVW];

// ---------------- helpers ----------------
static __device__ __forceinline__ uint32_t smem_u32(const void* p) {
    uint32_t a;
    asm("{ .reg .u64 t; cvta.to.shared.u64 t, %1; cvt.u32.u64 %0, t; }"
        : "=r"(a) : "l"(p));
    return a;
}
static __device__ __forceinline__ void ldsm4(uint32_t* r, uint32_t addr) {
    asm volatile("ldmatrix.sync.aligned.m8n8.x4.shared.b16 {%0,%1,%2,%3}, [%4];"
                 : "=r"(r[0]), "=r"(r[1]), "=r"(r[2]), "=r"(r[3]) : "r"(addr));
}
static __device__ __forceinline__ void mma_bf16(float* c, const uint32_t* a,
                                                const uint32_t* b) {
    asm volatile(
        "mma.sync.aligned.m16n8k16.row.col.f32.bf16.bf16.f32 "
        "{%0,%1,%2,%3}, {%4,%5,%6,%7}, {%8,%9}, {%0,%1,%2,%3};"
        : "+f"(c[0]), "+f"(c[1]), "+f"(c[2]), "+f"(c[3])
        : "r"(a[0]), "r"(a[1]), "r"(a[2]), "r"(a[3]), "r"(b[0]), "r"(b[1]));
}
static __device__ __forceinline__ void cpa(uint32_t dst, const void* src) {
    asm volatile("cp.async.cg.shared.global [%0], [%1], 16;" :: "r"(dst), "l"(src));
}
static __device__ __forceinline__ uint32_t sw_off(int row, int kchunk) {
    return (uint32_t)(row * 64 + ((kchunk ^ ((row >> 1) & 3)) << 4));
}
static __device__ __forceinline__ void split1(float v, __nv_bfloat16& h,
                                              __nv_bfloat16& l) {
    h = __float2bfloat16(v);
    l = __float2bfloat16(v - __bfloat162float(h));
}

// ---------------- shared HMMA mainloop: 3-stage cp.async pipeline ----------------
#define GBM 128
#define GBN 128
#define STG 32768
#define SM_DYN (3 * STG)

static __device__ __forceinline__ void mma_loop(
    const __nv_bfloat16* __restrict__ Ah, const __nv_bfloat16* __restrict__ Al,
    const __nv_bfloat16* __restrict__ Bh, const __nv_bfloat16* __restrict__ Bl,
    int m0, int n0, int N, int Kst, int NK, char* smem, float acc[4][4][4]) {
    const uint32_t sb = smem_u32(smem);
    const int tid = threadIdx.x;
    const int lane = tid & 31;
    const int w = tid >> 5;
    const int wm = (w & 1) * 64;
    const int wn = (w >> 1) * 32;
    const int r8  = lane & 7;
    const int oct = lane >> 3;

#define ISSUE(IT) do {                                                        \
        int kt = (IT) << 5;                                                   \
        int bufo = ((IT) % 3) * STG;                                          \
        char* st = smem + bufo;                                               \
        uint32_t stu = sb + bufo;                                             \
        _Pragma("unroll")                                                     \
        for (int i = 0; i < 2; i++) {                                         \
            int idx = tid + (i << 8);                                         \
            int row = idx >> 2, cq = idx & 3;                                 \
            uint32_t off = sw_off(row, cq);                                   \
            size_t ga = (size_t)(m0 + row) * Kst + kt + (cq << 3);            \
            cpa(stu + off, Ah + ga);                                          \
            cpa(stu + 8192 + off, Al + ga);                                   \
            int n = n0 + row;                                                 \
            if (n < N) {                                                      \
                size_t gb = (size_t)n * Kst + kt + (cq << 3);                 \
                cpa(stu + 16384 + off, Bh + gb);                              \
                cpa(stu + 24576 + off, Bl + gb);                              \
            } else {                                                          \
                uint4 z4 = make_uint4(0, 0, 0, 0);                            \
                *(uint4*)(st + 16384 + off) = z4;                             \
                *(uint4*)(st + 24576 + off) = z4;                             \
            }                                                                 \
        }                                                                     \
        asm volatile("cp.async.commit_group;" ::: "memory");                  \
    } while (0)

    ISSUE(0);
    if (NK > 1) ISSUE(1);
    for (int it = 0; it < NK; it++) {
        if (it + 1 < NK) asm volatile("cp.async.wait_group 1;" ::: "memory");
        else             asm volatile("cp.async.wait_group 0;" ::: "memory");
        __syncthreads();
        if (it + 2 < NK) ISSUE(it + 2);

        const uint32_t base = sb + (it % 3) * STG;
        #pragma unroll
        for (int ks = 0; ks < 2; ks++) {
            uint32_t bH[4][2], bL[4][2], aF[4][4];
            #pragma unroll
            for (int p = 0; p < 2; p++) {
                int n = wn + p * 16 + (oct >> 1) * 8 + r8;
                int kc = ks * 2 + (oct & 1);
                uint32_t ad = base + 16384 + sw_off(n, kc);
                uint32_t t[4];
                ldsm4(t, ad);
                bH[p * 2][0] = t[0]; bH[p * 2][1] = t[1];
                bH[p * 2 + 1][0] = t[2]; bH[p * 2 + 1][1] = t[3];
                ldsm4(t, ad + 8192);
                bL[p * 2][0] = t[0]; bL[p * 2][1] = t[1];
                bL[p * 2 + 1][0] = t[2]; bL[p * 2 + 1][1] = t[3];
            }
            #pragma unroll
            for (int mt = 0; mt < 4; mt++) {
                int row = wm + mt * 16 + (oct & 1) * 8 + r8;
                int kc = ks * 2 + (oct >> 1);
                ldsm4(aF[mt], base + sw_off(row, kc));
            }
            #pragma unroll
            for (int mt = 0; mt < 4; mt++)
                #pragma unroll
                for (int nt = 0; nt < 4; nt++) {
                    mma_bf16(acc[mt][nt], aF[mt], bH[nt]);
                    mma_bf16(acc[mt][nt], aF[mt], bL[nt]);
                }
            #pragma unroll
            for (int mt = 0; mt < 4; mt++) {
                int row = wm + mt * 16 + (oct & 1) * 8 + r8;
                int kc = ks * 2 + (oct >> 1);
                ldsm4(aF[mt], base + 8192 + sw_off(row, kc));
            }
            #pragma unroll
            for (int mt = 0; mt < 4; mt++)
                #pragma unroll
                for (int nt = 0; nt < 4; nt++)
                    mma_bf16(acc[mt][nt], aF[mt], bH[nt]);
        }
    }
#undef ISSUE
    __syncthreads();
}

// ---------------- embedding ----------------
__global__ void embed_kernel(const int* __restrict__ ids,
                             const float* __restrict__ tok,
                             const float* __restrict__ pos) {
    int i = blockIdx.x * blockDim.x + threadIdx.x;
    if (i >= NTOK * DM) return;
    int row = i / DM, d = i - row * DM;
    int t = row % TSEQ;
    g_x[i] = tok[(size_t)ids[row] * DM + d] + pos[t * DM + d];
}

// ---------------- weight repack: [K,N] fp32 -> [N,K] bf16 hi/lo (64x64 tiles) ----------------
// float4 read path only when N % 4 == 0 (misaligned otherwise: VCAB is odd).
__global__ void __launch_bounds__(256)
repack_t(const float* __restrict__ src,
         __nv_bfloat16* __restrict__ dh,
         __nv_bfloat16* __restrict__ dl, int K, int N) {
    __shared__ float s[64][65];
    size_t mo = (size_t)blockIdx.z * K * N;
    int n0 = blockIdx.x * 64, k0 = blockIdx.y * 64;
    int t = threadIdx.x;
    bool vec = (n0 + 64 <= N) && ((N & 3) == 0);
    #pragma unroll
    for (int p = 0; p < 4; p++) {
        int k = p * 16 + (t >> 4);
        int nl = (t & 15) * 4;
        if (vec) {
            float4 v = *(const float4*)(src + mo + (size_t)(k0 + k) * N + n0 + nl);
            s[nl][k] = v.x; s[nl + 1][k] = v.y; s[nl + 2][k] = v.z; s[nl + 3][k] = v.w;
        } else {
            #pragma unroll
            for (int j = 0; j < 4; j++) {
                int n = n0 + nl + j;
                s[nl + j][k] = (n < N) ? src[mo + (size_t)(k0 + k) * N + n] : 0.f;
            }
        }
    }
    __syncthreads();
    #pragma unroll
    for (int p = 0; p < 2; p++) {
        int nl = p * 32 + (t >> 3);
        int kl = (t & 7) * 8;
        int n = n0 + nl;
        if (n >= N) continue;
        __nv_bfloat16 hs[8], ls[8];
        #pragma unroll
        for (int j = 0; j < 8; j++) split1(s[nl][kl + j], hs[j], ls[j]);
        size_t o = mo + (size_t)n * K + k0 + kl;
        *(uint4*)(dh + o) = *(uint4*)hs;
        *(uint4*)(dl + o) = *(uint4*)ls;
    }
}

// qkv: [L,H,D,HD] -> per layer combined [q|k|v][2304, 768] bf16 hi/lo
__global__ void repack_qkv_t(const float* __restrict__ wq,
                             const float* __restrict__ wk,
                             const float* __restrict__ wv) {
    __shared__ float tq[32][33], tk[32][33], tv[32][33];
    int z = blockIdx.z, l = z / NH, h = z % NH;
    int d0 = blockIdx.y * 32, e0 = blockIdx.x * 32;
    int tx = threadIdx.x, ty = threadIdx.y;
    size_t sbo = ((size_t)l * NH + h) * DM * HDIM;
    for (int i = ty; i < 32; i += 8) {
        int d = d0 + i, e = e0 + tx;
        size_t idx = sbo + (size_t)d * HDIM + e;
        tq[i][tx] = wq[idx]; tk[i][tx] = wk[idx]; tv[i][tx] = wv[idx];
    }
    __syncthreads();
    size_t db = (size_t)l * QKVW * DM;
    for (int i = ty; i < 32; i += 8) {
        int e = e0 + i, d = d0 + tx;
        int nq = h * HDIM + e;
        __nv_bfloat16 hh, ll;
        size_t o;
        o = db + (size_t)nq * DM + d;
        split1(tq[tx][i], hh, ll); g_tqkv_h[o] = hh; g_tqkv_l[o] = ll;
        o = db + (size_t)(DM + nq) * DM + d;
        split1(tk[tx][i], hh, ll); g_tqkv_h[o] = hh; g_tqkv_l[o] = ll;
        o = db + (size_t)(2 * DM + nq) * DM + d;
        split1(tv[tx][i], hh, ll); g_tqkv_h[o] = hh; g_tqkv_l[o] = ll;
    }
}

__global__ void bias_concat(const float* __restrict__ bq,
                            const float* __restrict__ bk,
                            const float* __restrict__ bv) {
    int i = blockIdx.x * blockDim.x + threadIdx.x;
    if (i >= NL * QKVW) return;
    int l = i / QKVW, c = i % QKVW;
    float v = (c < DM) ? bq[l * DM + c]
            : (c < 2 * DM) ? bk[l * DM + c - DM]
            : bv[l * DM + c - 2 * DM];
    g_bqkv[i] = v;
}

// ---------------- layernorm: fp32 in -> split bf16 out ----------------
__global__ void ln_kernel(const float* __restrict__ in,
                          __nv_bfloat16* __restrict__ oh,
                          __nv_bfloat16* __restrict__ ol,
                          const float* __restrict__ g, const float* __restrict__ b) {
    int row = blockIdx.x;
    const float* x = in + (size_t)row * DM;
    float s = 0.f, s2 = 0.f;
    for (int i = threadIdx.x; i < DM; i += blockDim.x) {
        float v = x[i];
        s += v; s2 += v * v;
    }
    __shared__ float rs[32], rs2[32];
    for (int o = 16; o; o >>= 1) {
        s  += __shfl_down_sync(0xffffffffu, s, o);
        s2 += __shfl_down_sync(0xffffffffu, s2, o);
    }
    int wid = threadIdx.x >> 5, lid = threadIdx.x & 31;
    if (lid == 0) { rs[wid] = s; rs2[wid] = s2; }
    __syncthreads();
    if (wid == 0) {
        int nw = blockDim.x >> 5;
        s  = (lid < nw) ? rs[lid]  : 0.f;
        s2 = (lid < nw) ? rs2[lid] : 0.f;
        for (int o = 16; o; o >>= 1) {
            s  += __shfl_down_sync(0xffffffffu, s, o);
            s2 += __shfl_down_sync(0xffffffffu, s2, o);
        }
        if (lid == 0) { rs[0] = s; rs2[0] = s2; }
    }
    __syncthreads();
    float mean = rs[0] * (1.f / DM);
    float var  = rs2[0] * (1.f / DM) - mean * mean;
    float inv  = rsqrtf(var + 1e-5f);
    for (int i = threadIdx.x; i < DM; i += blockDim.x) {
        float v = (x[i] - mean) * inv * g[i] + b[i];
        __nv_bfloat16 h, l;
        split1(v, h, l);
        oh[(size_t)row * DM + i] = h;
        ol[(size_t)row * DM + i] = l;
    }
}

// ---------------- split fp32 activation -> bf16 hi/lo ----------------
__global__ void split_act(const float* __restrict__ x,
                          __nv_bfloat16* __restrict__ oh,
                          __nv_bfloat16* __restrict__ ol, int n) {
    int i = blockIdx.x * blockDim.x + threadIdx.x;
    if (i >= n) return;
    __nv_bfloat16 h, l;
    split1(x[i], h, l);
    oh[i] = h; ol[i] = l;
}

// ---------------- weight GEMM kernel ----------------
__global__ void __launch_bounds__(256, 2)
gemm_mma(const __nv_bfloat16* __restrict__ Ah, const __nv_bfloat16* __restrict__ Al,
         const __nv_bfloat16* __restrict__ Bh, const __nv_bfloat16* __restrict__ Bl,
         float* __restrict__ C, __nv_bfloat16* __restrict__ Ch,
         __nv_bfloat16* __restrict__ Cl, int N, int K,
         const float* __restrict__ bias, const float* __restrict__ res,
         int relu, int mode) {
    extern __shared__ char smem[];
    const int m0 = blockIdx.x * GBM;
    const int n0 = blockIdx.y * GBN;
    float acc[4][4][4] = {};
    mma_loop(Ah, Al, Bh, Bl, m0, n0, N, K, K >> 5, smem, acc);

    const int tid = threadIdx.x;
    const int lane = tid & 31;
    const int w = tid >> 5;
    const int wm = (w & 1) * 64;
    const int wn = (w >> 1) * 32;
    const int g2 = lane >> 2;
    const int t2 = (lane & 3) * 2;

    if (mode == 0) {
        const bool fast = (n0 + GBN <= N) && ((N & 1) == 0);
        #pragma unroll
        for (int mt = 0; mt < 4; mt++) {
            #pragma unroll
            for (int nt = 0; nt < 4; nt++) {
                float* c = acc[mt][nt];
                int row = m0 + wm + mt * 16 + g2;
                int col = n0 + wn + nt * 8 + t2;
                if (fast) {
                    float2 v0 = make_float2(c[0], c[1]);
                    float2 v1 = make_float2(c[2], c[3]);
                    if (bias) {
                        float2 bb = *(const float2*)(bias + col);
                        v0.x += bb.x; v0.y += bb.y; v1.x += bb.x; v1.y += bb.y;
                    }
                    if (res) {
                        float2 r0 = *(const float2*)(res + (size_t)row * N + col);
                        float2 r1 = *(const float2*)(res + (size_t)(row + 8) * N + col);
                        v0.x += r0.x; v0.y += r0.y; v1.x += r1.x; v1.y += r1.y;
                    }
                    if (relu) {
                        v0.x = fmaxf(v0.x, 0.f); v0.y = fmaxf(v0.y, 0.f);
                        v1.x = fmaxf(v1.x, 0.f); v1.y = fmaxf(v1.y, 0.f);
                    }
                    *(float2*)(C + (size_t)row * N + col) = v0;
                    *(float2*)(C + (size_t)(row + 8) * N + col) = v1;
                } else {
                    #pragma unroll
                    for (int e = 0; e < 2; e++) {
                        int nn = col + e;
                        if (nn < N) {
                            float v0 = c[e], v1 = c[2 + e];
                            if (bias) { float bb = bias[nn]; v0 += bb; v1 += bb; }
                            if (res) {
                                v0 += res[(size_t)row * N + nn];
                                v1 += res[(size_t)(row + 8) * N + nn];
                            }
                            if (relu) { v0 = fmaxf(v0, 0.f); v1 = fmaxf(v1, 0.f); }
                            C[(size_t)row * N + nn] = v0;
                            C[(size_t)(row + 8) * N + nn] = v1;
                        }
                    }
                }
            }
        }
    } else if (mode == 1) {
        #pragma unroll
        for (int mt = 0; mt < 4; mt++) {
            #pragma unroll
            for (int nt = 0; nt < 4; nt++) {
                float* c = acc[mt][nt];
                int row = m0 + wm + mt * 16 + g2;
                int col = n0 + wn + nt * 8 + t2;
                float v[4] = {c[0], c[1], c[2], c[3]};
                if (bias) {
                    float2 bb = *(const float2*)(bias + col);
                    v[0] += bb.x; v[1] += bb.y; v[2] += bb.x; v[3] += bb.y;
                }
                if (relu) {
                    v[0] = fmaxf(v[0], 0.f); v[1] = fmaxf(v[1], 0.f);
                    v[2] = fmaxf(v[2], 0.f); v[3] = fmaxf(v[3], 0.f);
                }
                __nv_bfloat16 h0, l0, h1, l1;
                split1(v[0], h0, l0); split1(v[1], h1, l1);
                *(__nv_bfloat162*)(Ch + (size_t)row * N + col) = __halves2bfloat162(h0, h1);
                *(__nv_bfloat162*)(Cl + (size_t)row * N + col) = __halves2bfloat162(l0, l1);
                split1(v[2], h0, l0); split1(v[3], h1, l1);
                *(__nv_bfloat162*)(Ch + (size_t)(row + 8) * N + col) = __halves2bfloat162(h0, h1);
                *(__nv_bfloat162*)(Cl + (size_t)(row + 8) * N + col) = __halves2bfloat162(l0, l1);
            }
        }
    } else {
        // qkv scatter: N == 2304
        #pragma unroll
        for (int mt = 0; mt < 4; mt++) {
            #pragma unroll
            for (int nt = 0; nt < 4; nt++) {
                float* c = acc[mt][nt];
                int row = m0 + wm + mt * 16 + g2;
                int col = n0 + wn + nt * 8 + t2;
                float2 bb = *(const float2*)(bias + col);
                #pragma unroll
                for (int e = 0; e < 4; e++) {
                    int r = row + (e >> 1) * 8;
                    int cc = col + (e & 1);
                    float v = c[e] + ((e & 1) ? bb.y : bb.x);
                    int b = r >> 9, s = r & 511;
                    int sec = cc / DM, d = cc - sec * DM;
                    int h = d >> 6, ee = d & 63;
                    __nv_bfloat16 hh, ll;
                    split1(v, hh, ll);
                    size_t zo = (size_t)(b * NH + h);
                    if (sec == 0) {
                        size_t o = (zo * TSEQ + s) * HDIM + ee;
                        g_qh[o] = hh; g_ql[o] = ll;
                    } else if (sec == 1) {
                        size_t o = (zo * TSEQ + s) * HDIM + ee;
                        g_kh[o] = hh; g_kl[o] = ll;
                    } else {
                        size_t o = (zo * HDIM + ee) * TSEQ + s;
                        g_vth[o] = hh; g_vtl[o] = ll;
                    }
                }
            }
        }
    }
}

// ---------------- attention scores: HMMA, lower-triangular blocks only ----------------
__global__ void __launch_bounds__(256, 2)
attn_sc() {
    extern __shared__ char smem[];
    const int mi_t[10] = {0, 1, 1, 2, 2, 2, 3, 3, 3, 3};
    const int ni_t[10] = {0, 0, 1, 0, 1, 2, 0, 1, 2, 3};
    int z = blockIdx.z;
    int mi = mi_t[blockIdx.x], ni = ni_t[blockIdx.x];
    const __nv_bfloat16* Ah = g_kh + (size_t)z * TSEQ * HDIM;
    const __nv_bfloat16* Al = g_kl + (size_t)z * TSEQ * HDIM;
    const __nv_bfloat16* Bh = g_qh + (size_t)z * TSEQ * HDIM;
    const __nv_bfloat16* Bl = g_ql + (size_t)z * TSEQ * HDIM;
    float acc[4][4][4] = {};
    mma_loop(Ah, Al, Bh, Bl, mi * 128, ni * 128, TSEQ, HDIM, 2, smem, acc);

    const int tid = threadIdx.x;
    const int lane = tid & 31;
    const int w = tid >> 5;
    const int wm = (w & 1) * 64;
    const int wn = (w >> 1) * 32;
    const int g2 = lane >> 2;
    const int t2 = (lane & 3) * 2;
    float* Cs = g_scores + (size_t)z * TSEQ * TSEQ;
    #pragma unroll
    for (int mt = 0; mt < 4; mt++) {
        #pragma unroll
        for (int nt = 0; nt < 4; nt++) {
            float* c = acc[mt][nt];
            int row = mi * 128 + wm + mt * 16 + g2;
            int col = ni * 128 + wn + nt * 8 + t2;
            *(float2*)(Cs + (size_t)row * TSEQ + col) = make_float2(c[0], c[1]);
            *(float2*)(Cs + (size_t)(row + 8) * TSEQ + col) = make_float2(c[2], c[3]);
        }
    }
}

// ---------------- causal softmax: fp32 scores -> split bf16 P ----------------
__global__ void softmax_kernel() {
    int rowg = blockIdx.x;
    int t = rowg & (TSEQ - 1);
    const float* w = g_scores + (size_t)rowg * TSEQ;
    int tid = threadIdx.x;
    bool val0 = (tid <= t), val1 = (tid + 256 <= t);
    float v0 = val0 ? w[tid] : -FLT_MAX;
    float v1 = val1 ? w[tid + 256] : -FLT_MAX;
    __shared__ float sh[256];
    sh[tid] = fmaxf(v0, v1);
    __syncthreads();
    for (int o = 128; o; o >>= 1) {
        if (tid < o) sh[tid] = fmaxf(sh[tid], sh[tid + o]);
        __syncthreads();
    }
    float m = sh[0];
    __syncthreads();
    float e0 = val0 ? expf(v0 - m) : 0.f;
    float e1 = val1 ? expf(v1 - m) : 0.f;
    sh[tid] = e0 + e1;
    __syncthreads();
    for (int o = 128; o; o >>= 1) {
        if (tid < o) sh[tid] += sh[tid + o];
        __syncthreads();
    }
    float inv = 1.f / sh[0];
    size_t ob = (size_t)rowg * TSEQ;
    int lim = ((t >> 7) + 1) << 7;   // causal block boundary
    __nv_bfloat16 h, l;
    if (tid < lim) {
        split1(e0 * inv, h, l);
        g_ph[ob + tid] = h; g_pl[ob + tid] = l;
    }
    if (tid + 256 < lim) {
        split1(e1 * inv, h, l);
        g_ph[ob + tid + 256] = h; g_pl[ob + tid + 256] = l;
    }
}

// ---------------- attention AV: HMMA, K truncated at diagonal ----------------
__global__ void __launch_bounds__(256, 2)
attn_av() {
    extern __shared__ char smem[];
    int z = blockIdx.z, b = z / NH, h = z % NH;
    int mi = blockIdx.x;
    const __nv_bfloat16* Ah = g_ph + (size_t)z * TSEQ * TSEQ;
    const __nv_bfloat16* Al = g_pl + (size_t)z * TSEQ * TSEQ;
    const __nv_bfloat16* Bh = g_vth + (size_t)z * HDIM * TSEQ;
    const __nv_bfloat16* Bl = g_vtl + (size_t)z * HDIM * TSEQ;
    float acc[4][4][4] = {};
    mma_loop(Ah, Al, Bh, Bl, mi * 128, 0, HDIM, TSEQ, (mi + 1) * 4, smem, acc);

    const int tid = threadIdx.x;
    const int lane = tid & 31;
    const int w = tid >> 5;
    const int wm = (w & 1) * 64;
    const int wn = (w >> 1) * 32;
    const int g2 = lane >> 2;
    const int t2 = (lane & 3) * 2;
    if (wn >= HDIM) return;
    #pragma unroll
    for (int mt = 0; mt < 4; mt++) {
        #pragma unroll
        for (int nt = 0; nt < 4; nt++) {
            int col = wn + nt * 8 + t2;
            if (col >= HDIM) continue;
            float* c = acc[mt][nt];
            int t = mi * 128 + wm + mt * 16 + g2;
            size_t o0 = (size_t)(b * TSEQ + t) * DM + h * HDIM + col;
            size_t o1 = (size_t)(b * TSEQ + t + 8) * DM + h * HDIM + col;
            __nv_bfloat16 h0, l0, h1, l1;
            split1(c[0], h0, l0); split1(c[1], h1, l1);
            *(__nv_bfloat162*)(g_ath + o0) = __halves2bfloat162(h0, h1);
            *(__nv_bfloat162*)(g_atl + o0) = __halves2bfloat162(l0, l1);
            split1(c[2], h0, l0); split1(c[3], h1, l1);
            *(__nv_bfloat162*)(g_ath + o1) = __halves2bfloat162(h0, h1);
            *(__nv_bfloat162*)(g_atl + o1) = __halves2bfloat162(l0, l1);
        }
    }
}

// ---------------- loss ----------------
__global__ void loss_kernel(const float* __restrict__ logits,
                            const int* __restrict__ target) {
    int row = blockIdx.x;
    const float* lg = logits + (size_t)row * VCAB;
    int tid = threadIdx.x;
    float m = -FLT_MAX, s = 0.f;
    for (int i = tid; i < VCAB; i += blockDim.x) {
        float v = lg[i];
        if (v > m) { s = s * expf(m - v) + 1.f; m = v; }
        else       { s += expf(v - m); }
    }
    __shared__ float sm[256], ss[256];
    sm[tid] = m; ss[tid] = s;
    __syncthreads();
    for (int o = 128; o; o >>= 1) {
        if (tid < o) {
            float m2 = sm[tid + o], s2 = ss[tid + o];
            float mm = fmaxf(sm[tid], m2);
            ss[tid] = ss[tid] * expf(sm[tid] - mm) + s2 * expf(m2 - mm);
            sm[tid] = mm;
        }
        __syncthreads();
    }
    if (tid == 0) {
        float lse = sm[0] + logf(ss[0]);
        g_nll[row] = lse - lg[target[row]];
    }
}

__global__ void loss_reduce(float* out) {
    __shared__ float sh[256];
    float s = 0.f;
    for (int i = threadIdx.x; i < NTOK; i += 256) s += g_nll[i];
    sh[threadIdx.x] = s;
    __syncthreads();
    for (int o = 128; o; o >>= 1) {
        if (threadIdx.x < o) sh[threadIdx.x] += sh[threadIdx.x + o];
        __syncthreads();
    }
    if (threadIdx.x == 0) out[0] = sh[0] * (1.f / NTOK);
}

// ---------------- host ----------------
extern "C" void kernel_launch(void* const* d_in, const int* in_sizes, int n_in,
                              void* d_out, int out_size) {
    const int*   x_ids      = (const int*)d_in[0];
    const int*   target     = (const int*)d_in[1];
    const float* tok_emb    = (const float*)d_in[2];
    const float* pos_emb    = (const float*)d_in[3];
    const float* in_proj_w  = (const float*)d_in[4];
    const float* in_proj_b  = (const float*)d_in[5];
    const float* wk         = (const float*)d_in[6];
    const float* bk         = (const float*)d_in[7];
    const float* wq         = (const float*)d_in[8];
    const float* bq         = (const float*)d_in[9];
    const float* wv         = (const float*)d_in[10];
    const float* bv         = (const float*)d_in[11];
    const float* out_proj_w = (const float*)d_in[12];
    const float* out_proj_b = (const float*)d_in[13];
    const float* ff_w1      = (const float*)d_in[14];
    const float* ff_b1      = (const float*)d_in[15];
    const float* ff_w2      = (const float*)d_in[16];
    const float* ff_b2      = (const float*)d_in[17];
    const float* lna_g      = (const float*)d_in[18];
    const float* lna_b      = (const float*)d_in[19];
    const float* lnf_g      = (const float*)d_in[20];
    const float* lnf_b      = (const float*)d_in[21];
    const float* out_w      = (const float*)d_in[22];
    const float* out_b      = (const float*)d_in[23];

    float *px, *plog, *pbqkv;
    cudaGetSymbolAddress((void**)&px,    g_x);
    cudaGetSymbolAddress((void**)&plog,  g_logits_scratch);
    cudaGetSymbolAddress((void**)&pbqkv, g_bqkv);

    __nv_bfloat16 *ah, *al, *h2h, *h2l, *ath, *atl, *ffh, *ffl;
    cudaGetSymbolAddress((void**)&ah,  g_ah);  cudaGetSymbolAddress((void**)&al,  g_al);
    cudaGetSymbolAddress((void**)&h2h, g_h2h); cudaGetSymbolAddress((void**)&h2l, g_h2l);
    cudaGetSymbolAddress((void**)&ath, g_ath); cudaGetSymbolAddress((void**)&atl, g_atl);
    cudaGetSymbolAddress((void**)&ffh, g_ffh); cudaGetSymbolAddress((void**)&ffl, g_ffl);

    __nv_bfloat16 *tqkv_h, *tqkv_l, *tin_h, *tin_l, *top_h, *top_l;
    __nv_bfloat16 *tf1_h, *tf1_l, *tf2_h, *tf2_l, *tow_h, *tow_l;
    cudaGetSymbolAddress((void**)&tqkv_h, g_tqkv_h); cudaGetSymbolAddress((void**)&tqkv_l, g_tqkv_l);
    cudaGetSymbolAddress((void**)&tin_h, g_tin_h); cudaGetSymbolAddress((void**)&tin_l, g_tin_l);
    cudaGetSymbolAddress((void**)&top_h, g_top_h); cudaGetSymbolAddress((void**)&top_l, g_top_l);
    cudaGetSymbolAddress((void**)&tf1_h, g_tf1_h); cudaGetSymbolAddress((void**)&tf1_l, g_tf1_l);
    cudaGetSymbolAddress((void**)&tf2_h, g_tf2_h); cudaGetSymbolAddress((void**)&tf2_l, g_tf2_l);
    cudaGetSymbolAddress((void**)&tow_h, g_tow_h); cudaGetSymbolAddress((void**)&tow_l, g_tow_l);

    cudaFuncSetAttribute(gemm_mma, cudaFuncAttributeMaxDynamicSharedMemorySize, SM_DYN);
    cudaFuncSetAttribute(attn_sc,  cudaFuncAttributeMaxDynamicSharedMemorySize, SM_DYN);
    cudaFuncSetAttribute(attn_av,  cudaFuncAttributeMaxDynamicSharedMemorySize, SM_DYN);

    const size_t LOGITS_N = (size_t)NTOK * VCAB;
    float* logits = ((size_t)out_size >= LOGITS_N) ? (float*)d_out : plog;

    dim3 tb(32, 8);
    dim3 blk(256);
    dim3 g_dm(NTOK / GBM, DM / GBN);
    dim3 g_qkvg(NTOK / GBM, QKVW / GBN);
    dim3 g_ff1(NTOK / GBM, DFF / GBN);
    dim3 g_lm(NTOK / GBM, (VCAB + GBN - 1) / GBN);
    dim3 g_sc(10, 1, NZ);
    dim3 g_av(TSEQ / GBM, 1, NZ);

    // launch order chosen so ncu (-s 5 -c 1) profiles gemm_mma at index 5
    embed_kernel<<<(NTOK * DM + 255) / 256, 256>>>(x_ids, tok_emb, pos_emb);   // 0
    repack_qkv_t<<<dim3(2, 24, NL * NH), tb>>>(wq, wk, wv);                    // 1
    bias_concat<<<(NL * QKVW + 255) / 256, 256>>>(bq, bk, bv);                 // 2
    repack_t<<<dim3(12, 12, NL), blk>>>(in_proj_w, tin_h, tin_l, DM, DM);      // 3
    ln_kernel<<<NTOK, 256>>>(px, ah, al, lna_g, lna_b);                        // 4
    gemm_mma<<<g_dm, blk, SM_DYN>>>(ah, al, tin_h, tin_l,                      // 5 <- profiled
                                    nullptr, h2h, h2l, DM, DM,
                                    in_proj_b, nullptr, 0, 1);
    // remaining repacks (independent; before first use)
    repack_t<<<dim3(12, 12, NL), blk>>>(out_proj_w, top_h, top_l, DM, DM);
    repack_t<<<dim3(48, 12, NL), blk>>>(ff_w1, tf1_h, tf1_l, DM, DFF);
    repack_t<<<dim3(12, 48, NL), blk>>>(ff_w2, tf2_h, tf2_l, DFF, DM);
    repack_t<<<dim3((VCAB + 63) / 64, 12, 1), blk>>>(out_w, tow_h, tow_l, DM, VCAB);

    for (int l = 0; l < NL; l++) {
        size_t wd = (size_t)l * DM * DM;
        size_t wqk = (size_t)l * QKVW * DM;
        size_t wf = (size_t)l * DM * DFF;
        if (l > 0) {
            ln_kernel<<<NTOK, 256>>>(px, ah, al, lna_g + l * DM, lna_b + l * DM);
            gemm_mma<<<g_dm, blk, SM_DYN>>>(ah, al, tin_h + wd, tin_l + wd,
                                            nullptr, h2h, h2l, DM, DM,
                                            in_proj_b + l * DM, nullptr, 0, 1);
        }
        gemm_mma<<<g_qkvg, blk, SM_DYN>>>(h2h, h2l, tqkv_h + wqk, tqkv_l + wqk,
                                          nullptr, nullptr, nullptr, QKVW, DM,
                                          pbqkv + l * QKVW, nullptr, 0, 2);
        attn_sc<<<g_sc, blk, SM_DYN>>>();
        softmax_kernel<<<NZ * TSEQ, 256>>>();
        attn_av<<<g_av, blk, SM_DYN>>>();
        gemm_mma<<<g_dm, blk, SM_DYN>>>(ath, atl, top_h + wd, top_l + wd,
                                        px, nullptr, nullptr, DM, DM,
                                        out_proj_b + l * DM, px, 0, 0);
        ln_kernel<<<NTOK, 256>>>(px, ah, al, lnf_g + l * DM, lnf_b + l * DM);
        gemm_mma<<<g_ff1, blk, SM_DYN>>>(ah, al, tf1_h + wf, tf1_l + wf,
                                         nullptr, ffh, ffl, DFF, DM,
                                         ff_b1 + l * DFF, nullptr, 1, 1);
        gemm_mma<<<g_dm, blk, SM_DYN>>>(ffh, ffl, tf2_h + wf, tf2_l + wf,
                                        px, nullptr, nullptr, DM, DFF,
                                        ff_b2 + l * DM, px, 0, 0);
    }

    split_act<<<(NTOK * DM + 255) / 256, 256>>>(px, ah, al, NTOK * DM);
    gemm_mma<<<g_lm, blk, SM_DYN>>>(ah, al, tow_h, tow_l,
                                    logits, nullptr, nullptr, VCAB, DM,
                                    out_b, nullptr, 0, 0);

    if ((size_t)out_size != LOGITS_N) {
        loss_kernel<<<NTOK, 256>>>(logits, target);
        loss_reduce<<<1, 256>>>((float*)d_out + (out_size - 1));
    }
}